// round 14
// baseline (speedup 1.0000x reference)
#include <cuda_runtime.h>
#include <cuda_bf16.h>
#include <cstdint>
#include <cstddef>
#include <cstring>

// ---------------- problem constants ----------------
#define NN       26
#define KDIM     676
#define KPAD     704          // 11 * 64
#define NCH8     11           // int8 K-chunks of 64
#define HID      256

// GAT output, int8 2-piece fixed point + per-element scale
__device__ signed char g_Aq1[16384 * KPAD];
__device__ signed char g_Aq2[16384 * KPAD];
__device__ float g_srow[16384];
// W1^T int8 2-piece: [256 n][KPAD k] + per-col scale
__device__ signed char g_Bq1[256 * KPAD];
__device__ signed char g_Bq2[256 * KPAD];
__device__ float g_tcol[256];
// GAT weights bf16 split (unchanged): [12 lh][32 o][40 f]
__device__ __nv_bfloat16 g_Wth[12 * 32 * 40];
__device__ __nv_bfloat16 g_Wtl[12 * 32 * 40];
__device__ float g_wsrc[12 * 32];
__device__ float g_wdst[12 * 32];

// ---------------- common helpers ----------------
__device__ __forceinline__ uint32_t smem_u32(const void* p) {
    uint32_t a;
    asm("{ .reg .u64 t; cvta.to.shared.u64 t, %1; cvt.u32.u64 %0, t; }" : "=r"(a) : "l"(p));
    return a;
}
__device__ __forceinline__ void ldsm4(uint32_t* d, uint32_t addr) {
    asm volatile("ldmatrix.sync.aligned.m8n8.x4.shared.b16 {%0,%1,%2,%3}, [%4];"
                 : "=r"(d[0]), "=r"(d[1]), "=r"(d[2]), "=r"(d[3]) : "r"(addr));
}
__device__ __forceinline__ void mma16816(float* c, const uint32_t* a, uint32_t b0, uint32_t b1) {
    asm volatile(
        "mma.sync.aligned.m16n8k16.row.col.f32.bf16.bf16.f32 "
        "{%0,%1,%2,%3}, {%4,%5,%6,%7}, {%8,%9}, {%0,%1,%2,%3};"
        : "+f"(c[0]), "+f"(c[1]), "+f"(c[2]), "+f"(c[3])
        : "r"(a[0]), "r"(a[1]), "r"(a[2]), "r"(a[3]), "r"(b0), "r"(b1));
}
__device__ __forceinline__ void imma16832(int* c, const uint32_t* a, uint32_t b0, uint32_t b1) {
    asm volatile(
        "mma.sync.aligned.m16n8k32.row.col.s32.s8.s8.s32 "
        "{%0,%1,%2,%3}, {%4,%5,%6,%7}, {%8,%9}, {%0,%1,%2,%3};"
        : "+r"(c[0]), "+r"(c[1]), "+r"(c[2]), "+r"(c[3])
        : "r"(a[0]), "r"(a[1]), "r"(a[2]), "r"(a[3]), "r"(b0), "r"(b1));
}
__device__ __forceinline__ void cp16(uint32_t dst, const void* src) {
    asm volatile("cp.async.ca.shared.global [%0], [%1], 16;" :: "r"(dst), "l"(src) : "memory");
}
#define CP_COMMIT() asm volatile("cp.async.commit_group;" ::: "memory")
#define CP_WAIT1()  asm volatile("cp.async.wait_group 1;" ::: "memory")
#define CP_WAIT0()  asm volatile("cp.async.wait_group 0;" ::: "memory")

__device__ __forceinline__ void split2(float a, float b, uint32_t& hi, uint32_t& lo) {
    __nv_bfloat162 h = __floats2bfloat162_rn(a, b);
    float ra = a - __bfloat162float(h.x);
    float rb = b - __bfloat162float(h.y);
    __nv_bfloat162 l = __floats2bfloat162_rn(ra, rb);
    memcpy(&hi, &h, 4);
    memcpy(&lo, &l, 4);
}
__device__ __forceinline__ float actelu(float v) {
    return v > 0.f ? v : (__expf(v) - 1.f);
}

// =====================================================================
// prep: GAT weight split + score vectors (bf16 path unchanged)
// =====================================================================
__global__ void prep_gatw(const float* __restrict__ W,
                          const float* __restrict__ a_src,
                          const float* __restrict__ a_dst)
{
    int i = blockIdx.x * 256 + threadIdx.x;
    if (i < 12 * 32 * 40) {
        int lh = i / 1280, r = i % 1280, o = r / 40, f = r % 40;
        float v = (o < 26 && f < 26) ? W[((size_t)lh * 26 + f) * 26 + o] : 0.f;
        __nv_bfloat16 h = __float2bfloat16_rn(v);
        g_Wth[i] = h;
        g_Wtl[i] = __float2bfloat16_rn(v - __bfloat162float(h));
        return;
    }
    int j = i - 12 * 32 * 40;
    if (j < 12 * 32) {
        int lh = j / 32, f = j % 32;
        float s = 0.f, d = 0.f;
        if (f < 26) {
            for (int o = 0; o < 26; o++) {
                float wv = W[((size_t)lh * 26 + f) * 26 + o];
                s = fmaf(wv, a_src[lh * 26 + o], s);
                d = fmaf(wv, a_dst[lh * 26 + o], d);
            }
        }
        g_wsrc[j] = s;
        g_wdst[j] = d;
    }
}

// prep: W1^T int8 2-piece quantization, per output-col scale
__global__ void prep_w1q(const float* __restrict__ W1)
{
    const int n = blockIdx.x;        // 0..255
    const int t = threadIdx.x;       // 128 threads
    __shared__ float red[128];
    float m = 0.f;
    for (int k = t; k < KDIM; k += 128)
        m = fmaxf(m, fabsf(W1[(size_t)k * HID + n]));
    red[t] = m;
    __syncthreads();
    for (int o = 64; o > 0; o >>= 1) {
        if (t < o) red[t] = fmaxf(red[t], red[t + o]);
        __syncthreads();
    }
    const float tv = fmaxf(red[0], 1e-20f);
    if (t == 0) g_tcol[n] = tv;
    const float qk = 127.f / tv;
    for (int k = t; k < KPAD; k += 128) {
        float w = (k < KDIM) ? W1[(size_t)k * HID + n] : 0.f;
        float u = w * qk;
        int q1 = __float2int_rn(u);
        int q2 = __float2int_rn((u - (float)q1) * 128.f);
        g_Bq1[(size_t)n * KPAD + k] = (signed char)q1;
        g_Bq2[(size_t)n * KPAD + k] = (signed char)q2;
    }
}

// =====================================================================
// GAT on tensor cores — R8 structure; epilogue emits int8 2-piece.
// =====================================================================
#define XTH 0
#define XTL 20480
#define APH 40960
#define APL 61440
#define WTH 81920
#define WTL 92160
#define SDST 102400
#define SWS 106496
#define SWD 107008
#define GAT_SMEM 107520

__global__ __launch_bounds__(256, 2)
void gat_tc(const float* __restrict__ x)
{
    extern __shared__ char sm[];
    const uint32_t sb = smem_u32(sm);
    const int tid = threadIdx.x, w = tid >> 5, lane = tid & 31;
    const int b = blockIdx.x * 8 + w;

    {
        uint4* p = (uint4*)(sm + XTH);
        for (int i = tid; i < (20480 * 2) / 16; i += 256)
            p[i] = make_uint4(0, 0, 0, 0);
    }
    __syncthreads();

    __nv_bfloat16* xth = (__nv_bfloat16*)(sm + XTH) + w * 1280;
    __nv_bfloat16* xtl = (__nv_bfloat16*)(sm + XTL) + w * 1280;
    __nv_bfloat16* aph = (__nv_bfloat16*)(sm + APH) + w * 1280;
    __nv_bfloat16* apl = (__nv_bfloat16*)(sm + APL) + w * 1280;
    float* sdst = (float*)(sm + SDST) + w * 128;
    float* sws  = (float*)(sm + SWS);
    float* swd  = (float*)(sm + SWD);

    for (int idx = lane; idx < KDIM; idx += 32) {
        int i = idx / 26, f = idx % 26;
        float v = x[(size_t)b * KDIM + idx];
        __nv_bfloat16 h = __float2bfloat16_rn(v);
        xth[f * 40 + i] = h;
        xtl[f * 40 + i] = __float2bfloat16_rn(v - __bfloat162float(h));
    }

    const int rpat = lane & 15;
    const int chalf = (lane >> 4) * 8;
    const uint32_t xthA = sb + XTH + w * 2560;
    const uint32_t xtlA = sb + XTL + w * 2560;
    const uint32_t aphA = sb + APH + w * 2560;
    const uint32_t aplA = sb + APL + w * 2560;

    for (int l = 0; l < 3; l++) {
        __syncthreads();
        {
            const uint4* s0 = (const uint4*)(g_Wth + l * 5120);
            const uint4* s1 = (const uint4*)(g_Wtl + l * 5120);
            uint4* d0 = (uint4*)(sm + WTH);
            uint4* d1 = (uint4*)(sm + WTL);
            for (int i = tid; i < 640; i += 256) { d0[i] = s0[i]; d1[i] = s1[i]; }
            if (tid < 128) {
                ((float*)(sm + SWS))[tid] = g_wsrc[l * 128 + tid];
                ((float*)(sm + SWD))[tid] = g_wdst[l * 128 + tid];
            }
        }
        __syncthreads();

        float ssrc[4];
        {
            float xi[26];
            #pragma unroll
            for (int f = 0; f < 26; f++)
                xi[f] = __bfloat162float(xth[f * 40 + lane]) +
                        __bfloat162float(xtl[f * 40 + lane]);
            #pragma unroll
            for (int h = 0; h < 4; h++) {
                float s = 0.f, d = 0.f;
                #pragma unroll
                for (int f = 0; f < 26; f++) {
                    s = fmaf(xi[f], sws[h * 32 + f], s);
                    d = fmaf(xi[f], swd[h * 32 + f], d);
                }
                ssrc[h] = s;
                sdst[h * 32 + lane] = d;
            }
        }
        __syncwarp();

        float outf[2][4][4];
        #pragma unroll
        for (int mt = 0; mt < 2; mt++)
            #pragma unroll
            for (int nt = 0; nt < 4; nt++)
                #pragma unroll
                for (int q = 0; q < 4; q++) outf[mt][nt][q] = 0.f;

        for (int h = 0; h < 4; h++) {
            float e[NN];
            float m = -1e30f;
            #pragma unroll
            for (int j = 0; j < NN; j++) {
                float v = ssrc[h] + sdst[h * 32 + j];
                v = fmaxf(v, 0.2f * v);
                e[j] = v;
                m = fmaxf(m, v);
            }
            float su = 0.f;
            #pragma unroll
            for (int j = 0; j < NN; j++) {
                float p = __expf(e[j] - m);
                e[j] = p;
                su += p;
            }
            const float inv = 1.0f / su;
            #pragma unroll
            for (int jj = 0; jj < 16; jj++) {
                float a0 = (2 * jj < 26) ? e[(2 * jj < 26) ? 2 * jj : 0] * inv : 0.f;
                float a1 = (2 * jj + 1 < 26) ? e[(2 * jj + 1 < 26) ? 2 * jj + 1 : 0] * inv : 0.f;
                uint32_t hi, lo;
                split2(a0, a1, hi, lo);
                *(uint32_t*)(aph + lane * 40 + 2 * jj) = hi;
                *(uint32_t*)(apl + lane * 40 + 2 * jj) = lo;
            }
            __syncwarp();

            float Yf[2][4][4];
            #pragma unroll
            for (int mt = 0; mt < 2; mt++)
                #pragma unroll
                for (int nt = 0; nt < 4; nt++)
                    #pragma unroll
                    for (int q = 0; q < 4; q++) Yf[mt][nt][q] = 0.f;

            #pragma unroll
            for (int ks = 0; ks < 2; ks++) {
                uint32_t Ah[2][4], Al[2][4], Xh[2][4], Xl[2][4];
                #pragma unroll
                for (int mt = 0; mt < 2; mt++) {
                    uint32_t off = (uint32_t)((mt * 16 + rpat) * 80 + (ks * 16 + chalf) * 2);
                    ldsm4(Ah[mt], aphA + off);
                    ldsm4(Al[mt], aplA + off);
                }
                #pragma unroll
                for (int nt = 0; nt < 2; nt++) {
                    uint32_t off = (uint32_t)((nt * 16 + rpat) * 80 + (ks * 16 + chalf) * 2);
                    ldsm4(Xh[nt], xthA + off);
                    ldsm4(Xl[nt], xtlA + off);
                }
                #pragma unroll
                for (int mt = 0; mt < 2; mt++)
                    #pragma unroll
                    for (int nt = 0; nt < 2; nt++) {
                        mma16816(Yf[mt][nt * 2],     Ah[mt], Xh[nt][0], Xh[nt][2]);
                        mma16816(Yf[mt][nt * 2 + 1], Ah[mt], Xh[nt][1], Xh[nt][3]);
                        mma16816(Yf[mt][nt * 2],     Ah[mt], Xl[nt][0], Xl[nt][2]);
                        mma16816(Yf[mt][nt * 2 + 1], Ah[mt], Xl[nt][1], Xl[nt][3]);
                        mma16816(Yf[mt][nt * 2],     Al[mt], Xh[nt][0], Xh[nt][2]);
                        mma16816(Yf[mt][nt * 2 + 1], Al[mt], Xh[nt][1], Xh[nt][3]);
                    }
            }

            uint32_t YAh[2][2][4], YAl[2][2][4];
            #pragma unroll
            for (int mt = 0; mt < 2; mt++)
                #pragma unroll
                for (int ks = 0; ks < 2; ks++) {
                    split2(Yf[mt][2 * ks][0],     Yf[mt][2 * ks][1],     YAh[mt][ks][0], YAl[mt][ks][0]);
                    split2(Yf[mt][2 * ks][2],     Yf[mt][2 * ks][3],     YAh[mt][ks][1], YAl[mt][ks][1]);
                    split2(Yf[mt][2 * ks + 1][0], Yf[mt][2 * ks + 1][1], YAh[mt][ks][2], YAl[mt][ks][2]);
                    split2(Yf[mt][2 * ks + 1][2], Yf[mt][2 * ks + 1][3], YAh[mt][ks][3], YAl[mt][ks][3]);
                }

            #pragma unroll
            for (int ks = 0; ks < 2; ks++) {
                uint32_t Wh[2][4], Wl[2][4];
                #pragma unroll
                for (int ot = 0; ot < 2; ot++) {
                    uint32_t off = (uint32_t)((ot * 16 + rpat) * 80 + (ks * 16 + chalf) * 2);
                    ldsm4(Wh[ot], sb + WTH + h * 2560 + off);
                    ldsm4(Wl[ot], sb + WTL + h * 2560 + off);
                }
                #pragma unroll
                for (int mt = 0; mt < 2; mt++)
                    #pragma unroll
                    for (int ot = 0; ot < 2; ot++) {
                        mma16816(outf[mt][ot * 2],     YAh[mt][ks], Wh[ot][0], Wh[ot][2]);
                        mma16816(outf[mt][ot * 2 + 1], YAh[mt][ks], Wh[ot][1], Wh[ot][3]);
                        mma16816(outf[mt][ot * 2],     YAh[mt][ks], Wl[ot][0], Wl[ot][2]);
                        mma16816(outf[mt][ot * 2 + 1], YAh[mt][ks], Wl[ot][1], Wl[ot][3]);
                        mma16816(outf[mt][ot * 2],     YAl[mt][ks], Wh[ot][0], Wh[ot][2]);
                        mma16816(outf[mt][ot * 2 + 1], YAl[mt][ks], Wh[ot][1], Wh[ot][3]);
                    }
            }
        } // heads

        const int g = lane >> 2, tc2 = (lane & 3) * 2;
        if (l < 2) {
            #pragma unroll
            for (int mt = 0; mt < 2; mt++)
                #pragma unroll
                for (int nt = 0; nt < 4; nt++) {
                    int col = nt * 8 + tc2;
                    if (col < 26) {
                        #pragma unroll
                        for (int hf = 0; hf < 2; hf++) {
                            int row = mt * 16 + g + hf * 8;
                            if (row < 26) {
                                float v0 = actelu(outf[mt][nt][hf * 2]     * 0.25f);
                                float v1 = actelu(outf[mt][nt][hf * 2 + 1] * 0.25f);
                                __nv_bfloat16 h0 = __float2bfloat16_rn(v0);
                                __nv_bfloat16 h1 = __float2bfloat16_rn(v1);
                                xth[col * 40 + row] = h0;
                                xtl[col * 40 + row] = __float2bfloat16_rn(v0 - __bfloat162float(h0));
                                xth[(col + 1) * 40 + row] = h1;
                                xtl[(col + 1) * 40 + row] = __float2bfloat16_rn(v1 - __bfloat162float(h1));
                            }
                        }
                    }
                }
        } else {
            // ---- final: int8 2-piece quantization, per-element scale ----
            float lm = 0.f;
            #pragma unroll
            for (int mt = 0; mt < 2; mt++)
                #pragma unroll
                for (int nt = 0; nt < 4; nt++) {
                    int col = nt * 8 + tc2;
                    if (col < 26) {
                        #pragma unroll
                        for (int hf = 0; hf < 2; hf++) {
                            int row = mt * 16 + g + hf * 8;
                            if (row < 26) {
                                float v0 = actelu(outf[mt][nt][hf * 2]     * 0.25f);
                                float v1 = actelu(outf[mt][nt][hf * 2 + 1] * 0.25f);
                                lm = fmaxf(lm, fmaxf(fabsf(v0), fabsf(v1)));
                            }
                        }
                    }
                }
            #pragma unroll
            for (int off = 16; off > 0; off >>= 1)
                lm = fmaxf(lm, __shfl_xor_sync(0xffffffffu, lm, off));
            const float s = fmaxf(lm, 1e-20f);
            if (lane == 0) g_srow[b] = s;
            const float qk = 127.f / s;

            #pragma unroll
            for (int mt = 0; mt < 2; mt++)
                #pragma unroll
                for (int nt = 0; nt < 4; nt++) {
                    int col = nt * 8 + tc2;
                    if (col < 26) {
                        #pragma unroll
                        for (int hf = 0; hf < 2; hf++) {
                            int row = mt * 16 + g + hf * 8;
                            if (row < 26) {
                                float v0 = actelu(outf[mt][nt][hf * 2]     * 0.25f);
                                float v1 = actelu(outf[mt][nt][hf * 2 + 1] * 0.25f);
                                float u0 = v0 * qk, u1 = v1 * qk;
                                int a1 = __float2int_rn(u0);
                                int a2 = __float2int_rn((u0 - (float)a1) * 128.f);
                                int b1 = __float2int_rn(u1);
                                int b2 = __float2int_rn((u1 - (float)b1) * 128.f);
                                size_t o = (size_t)b * KPAD + row * 26 + col;
                                char2 c1; c1.x = (signed char)a1; c1.y = (signed char)b1;
                                char2 c2; c2.x = (signed char)a2; c2.y = (signed char)b2;
                                *(char2*)&g_Aq1[o] = c1;
                                *(char2*)&g_Aq2[o] = c2;
                            }
                        }
                    }
                }
            if (lane < 28) {
                g_Aq1[(size_t)b * KPAD + KDIM + lane] = 0;
                g_Aq2[(size_t)b * KPAD + KDIM + lane] = 0;
            }
        }
    } // layers
}

// =====================================================================
// MLP on int8 IMMA (m16n8k32): 2-piece fixed point, half the MMAs.
// Block = 32 rows x 256 cols, 8 warps. K-chunks of 64 int8, 2-stage
// cp.async. Row stride 80B: 16B-aligned for cp.async AND conflict-free.
// =====================================================================
#define ASTG 2560             // 32 * 80
#define BSTG 20480            // 256 * 80
#define STG8 (2 * ASTG + 2 * BSTG)   // 46080
#define MLP_SMEM (2 * STG8)          // 92160
#define INVQ (1.f / (16256.f * 16256.f))

__device__ __forceinline__ void copy_chunk8(uint32_t smbase, int stage, int chunk,
                                            int row0, int tid)
{
    const uint32_t sbs = smbase + stage * STG8;
    #pragma unroll
    for (int k = 0; k < 9; k++) {
        int u = tid + k * 256;
        if (u < 256) {
            int t = u >> 7, r = (u & 127) >> 2, seg = u & 3;
            const signed char* base = t ? g_Aq2 : g_Aq1;
            const signed char* src = base + (size_t)(row0 + r) * KPAD + chunk * 64 + seg * 16;
            cp16(sbs + t * ASTG + r * 80 + seg * 16, src);
        } else {
            int v = u - 256;
            int t = v >> 10, r = (v & 1023) >> 2, seg = v & 3;
            const signed char* base = t ? g_Bq2 : g_Bq1;
            const signed char* src = base + (size_t)r * KPAD + chunk * 64 + seg * 16;
            cp16(sbs + 2 * ASTG + t * BSTG + r * 80 + seg * 16, src);
        }
    }
}

__global__ __launch_bounds__(256, 2)
void mlp_imma(const float* __restrict__ b1,
              const float* __restrict__ W2,
              const float* __restrict__ b2,
              float* __restrict__ out)
{
    extern __shared__ __align__(16) char dsm[];
    __shared__ float sb1[HID];
    __shared__ float st[HID];
    __shared__ float sW2[HID * 3];
    __shared__ float sb2s[3];
    __shared__ float ssr[32];
    __shared__ float red[32][13];

    const int tid = threadIdx.x, wid = tid >> 5, lane = tid & 31;
    const int warp_m = wid & 1;          // m16 tile
    const int warp_n = wid >> 1;         // 64-col slice
    const int row0 = blockIdx.x * 32;

    if (tid < HID) { sb1[tid] = b1[tid]; st[tid] = g_tcol[tid]; }
    for (int i = tid; i < HID * 3; i += 256) sW2[i] = W2[i];
    if (tid < 3) sb2s[tid] = b2[tid];
    if (tid < 32) ssr[tid] = g_srow[row0 + tid];

    const uint32_t smbase = smem_u32(dsm);

    int G1[8][4], G2[8][4];
    #pragma unroll
    for (int n8 = 0; n8 < 8; n8++)
        #pragma unroll
        for (int q = 0; q < 4; q++) { G1[n8][q] = 0; G2[n8][q] = 0; }

    copy_chunk8(smbase, 0, 0, row0, tid);
    CP_COMMIT();

    const int rpat = lane & 15;
    const int cb16 = (lane >> 4) * 16;   // byte offset of ldsm column half

    for (int c = 0; c < NCH8; c++) {
        const int s = c & 1;
        if (c + 1 < NCH8) {
            copy_chunk8(smbase, s ^ 1, c + 1, row0, tid);
            CP_COMMIT();
            CP_WAIT1();
        } else {
            CP_WAIT0();
        }
        __syncthreads();

        const uint32_t stB = smbase + s * STG8;
        #pragma unroll
        for (int kt = 0; kt < 2; kt++) {
            const uint32_t koff = (uint32_t)(kt * 32 + cb16);

            uint32_t aq1[4], aq2[4], bq1[4][4], bq2[4][4];
            {
                const uint32_t a_off = (uint32_t)(warp_m * 16 + rpat) * 80 + koff;
                ldsm4(aq1, stB + a_off);
                ldsm4(aq2, stB + ASTG + a_off);
            }
            #pragma unroll
            for (int np = 0; np < 4; np++) {
                const uint32_t b_off =
                    (uint32_t)(warp_n * 64 + np * 16 + rpat) * 80 + koff;
                ldsm4(bq1[np], stB + 2 * ASTG + b_off);
                ldsm4(bq2[np], stB + 2 * ASTG + BSTG + b_off);
            }

            #pragma unroll
            for (int np = 0; np < 4; np++)
                #pragma unroll
                for (int ss = 0; ss < 2; ss++) {
                    const int n8 = np * 2 + ss;
                    imma16832(G1[n8], aq1, bq1[np][ss], bq1[np][ss + 2]);
                    imma16832(G2[n8], aq1, bq2[np][ss], bq2[np][ss + 2]);
                    imma16832(G2[n8], aq2, bq1[np][ss], bq1[np][ss + 2]);
                }
        }
        __syncthreads();
    }

    // ---- epilogue: dequant + bias + lrelu + W2, reduce, store ----
    #pragma unroll
    for (int half = 0; half < 2; half++) {
        const int row = warp_m * 16 + (lane >> 2) + half * 8;
        const float sv = ssr[row] * INVQ;
        float s0 = 0.f, s1 = 0.f, s2 = 0.f;
        #pragma unroll
        for (int n8 = 0; n8 < 8; n8++) {
            const int col = warp_n * 64 + n8 * 8 + (lane & 3) * 2;
            float f0 = fmaf((float)G1[n8][half * 2 + 0], 16384.f,
                            128.f * (float)G2[n8][half * 2 + 0]);
            float f1 = fmaf((float)G1[n8][half * 2 + 1], 16384.f,
                            128.f * (float)G2[n8][half * 2 + 1]);
            float v0 = sv * st[col] * f0 + sb1[col];
            v0 = fmaxf(v0, 0.2f * v0);
            float v1 = sv * st[col + 1] * f1 + sb1[col + 1];
            v1 = fmaxf(v1, 0.2f * v1);
            s0 += v0 * sW2[col * 3 + 0] + v1 * sW2[(col + 1) * 3 + 0];
            s1 += v0 * sW2[col * 3 + 1] + v1 * sW2[(col + 1) * 3 + 1];
            s2 += v0 * sW2[col * 3 + 2] + v1 * sW2[(col + 1) * 3 + 2];
        }
        s0 += __shfl_xor_sync(0xffffffffu, s0, 1);
        s0 += __shfl_xor_sync(0xffffffffu, s0, 2);
        s1 += __shfl_xor_sync(0xffffffffu, s1, 1);
        s1 += __shfl_xor_sync(0xffffffffu, s1, 2);
        s2 += __shfl_xor_sync(0xffffffffu, s2, 1);
        s2 += __shfl_xor_sync(0xffffffffu, s2, 2);
        if ((lane & 3) == 0) {
            red[row][warp_n * 3 + 0] = s0;
            red[row][warp_n * 3 + 1] = s1;
            red[row][warp_n * 3 + 2] = s2;
        }
    }
    __syncthreads();
    if (tid < 32) {
        const int row = tid;
        #pragma unroll
        for (int oc = 0; oc < 3; oc++) {
            float v = red[row][oc] + red[row][3 + oc] + red[row][6 + oc] +
                      red[row][9 + oc] + sb2s[oc];
            out[(size_t)(row0 + row) * 3 + oc] = v;
        }
    }
}

// =====================================================================
// launch
// =====================================================================
extern "C" void kernel_launch(void* const* d_in, const int* in_sizes, int n_in,
                              void* d_out, int out_size)
{
    const float* x     = (const float*)d_in[1];
    const float* W     = (const float*)d_in[2];
    const float* a_src = (const float*)d_in[3];
    const float* a_dst = (const float*)d_in[4];
    const float* W1    = (const float*)d_in[5];
    const float* b1    = (const float*)d_in[6];
    const float* W2    = (const float*)d_in[7];
    const float* b2    = (const float*)d_in[8];
    float* out = (float*)d_out;

    const int batch = in_sizes[1] / KDIM;   // 16384

    cudaFuncSetAttribute(gat_tc, cudaFuncAttributeMaxDynamicSharedMemorySize, GAT_SMEM);
    cudaFuncSetAttribute(mlp_imma, cudaFuncAttributeMaxDynamicSharedMemorySize, MLP_SMEM);

    const int gw_total = 12 * 32 * 40 + 12 * 32;
    prep_gatw<<<(gw_total + 255) / 256, 256>>>(W, a_src, a_dst);
    prep_w1q<<<HID, 128>>>(W1);
    gat_tc<<<batch / 8, 256, GAT_SMEM>>>(x);
    mlp_imma<<<batch / 32, 256, MLP_SMEM>>>(b1, W2, b2, out);
    (void)n_in; (void)out_size;
}

// round 15
// speedup vs baseline: 1.0960x; 1.0960x over previous
#include <cuda_runtime.h>
#include <cuda_bf16.h>
#include <cstdint>
#include <cstddef>
#include <cstring>

// ---------------- problem constants ----------------
#define NN       26
#define KDIM     676
#define KPAD     704          // 22 * 32
#define NCHUNK   22
#define HID      256

// GAT output as bf16 hi/lo split [B, KPAD]
__device__ __nv_bfloat16 g_Ahi[16384 * KPAD];
__device__ __nv_bfloat16 g_Alo[16384 * KPAD];
// W1^T split: [256 n][KPAD k]
__device__ __nv_bfloat16 g_Bhi[256 * KPAD];
__device__ __nv_bfloat16 g_Blo[256 * KPAD];
// GAT weights, transposed + padded + split: [12 lh][32 o][40 f]
__device__ __nv_bfloat16 g_Wth[12 * 32 * 40];
__device__ __nv_bfloat16 g_Wtl[12 * 32 * 40];
// score vectors wsrc/wdst = W @ a_*: [12 lh][32 f]
__device__ float g_wsrc[12 * 32];
__device__ float g_wdst[12 * 32];

// ---------------- common helpers ----------------
__device__ __forceinline__ uint32_t smem_u32(const void* p) {
    uint32_t a;
    asm("{ .reg .u64 t; cvta.to.shared.u64 t, %1; cvt.u32.u64 %0, t; }" : "=r"(a) : "l"(p));
    return a;
}
__device__ __forceinline__ void ldsm4(uint32_t* d, uint32_t addr) {
    asm volatile("ldmatrix.sync.aligned.m8n8.x4.shared.b16 {%0,%1,%2,%3}, [%4];"
                 : "=r"(d[0]), "=r"(d[1]), "=r"(d[2]), "=r"(d[3]) : "r"(addr));
}
__device__ __forceinline__ void mma16816(float* c, const uint32_t* a, uint32_t b0, uint32_t b1) {
    asm volatile(
        "mma.sync.aligned.m16n8k16.row.col.f32.bf16.bf16.f32 "
        "{%0,%1,%2,%3}, {%4,%5,%6,%7}, {%8,%9}, {%0,%1,%2,%3};"
        : "+f"(c[0]), "+f"(c[1]), "+f"(c[2]), "+f"(c[3])
        : "r"(a[0]), "r"(a[1]), "r"(a[2]), "r"(a[3]), "r"(b0), "r"(b1));
}
__device__ __forceinline__ void cp16(uint32_t dst, const void* src) {
    asm volatile("cp.async.ca.shared.global [%0], [%1], 16;" :: "r"(dst), "l"(src) : "memory");
}
#define CP_COMMIT() asm volatile("cp.async.commit_group;" ::: "memory")
#define CP_WAIT1()  asm volatile("cp.async.wait_group 1;" ::: "memory")
#define CP_WAIT0()  asm volatile("cp.async.wait_group 0;" ::: "memory")

// split two floats into packed bf16x2 hi + lo correction
__device__ __forceinline__ void split2(float a, float b, uint32_t& hi, uint32_t& lo) {
    __nv_bfloat162 h = __floats2bfloat162_rn(a, b);
    float ra = a - __bfloat162float(h.x);
    float rb = b - __bfloat162float(h.y);
    __nv_bfloat162 l = __floats2bfloat162_rn(ra, rb);
    memcpy(&hi, &h, 4);
    memcpy(&lo, &l, 4);
}
__device__ __forceinline__ float actelu(float v) {
    return v > 0.f ? v : (__expf(v) - 1.f);
}
__device__ __forceinline__ void sts32(uint32_t addr, uint32_t v) {
    asm volatile("st.shared.b32 [%0], %1;" :: "r"(addr), "r"(v) : "memory");
}
__device__ __forceinline__ void sts16(uint32_t addr, uint16_t v) {
    asm volatile("st.shared.b16 [%0], %1;" :: "r"(addr), "h"(v) : "memory");
}

// =====================================================================
// merged prep kernel (R8)
// =====================================================================
__global__ void prep_all(const float* __restrict__ W1,
                         const float* __restrict__ W,
                         const float* __restrict__ a_src,
                         const float* __restrict__ a_dst)
{
    int i = blockIdx.x * 256 + threadIdx.x;
    if (i < 256 * KPAD) {
        int n = i / KPAD, k = i % KPAD;
        float v = (k < KDIM) ? W1[(size_t)k * HID + n] : 0.f;
        __nv_bfloat16 h = __float2bfloat16_rn(v);
        g_Bhi[i] = h;
        g_Blo[i] = __float2bfloat16_rn(v - __bfloat162float(h));
        return;
    }
    int u = i - 256 * KPAD;
    if (u < 12 * 32 * 40) {
        int lh = u / 1280, r = u % 1280, o = r / 40, f = r % 40;
        float v = (o < 26 && f < 26) ? W[((size_t)lh * 26 + f) * 26 + o] : 0.f;
        __nv_bfloat16 h = __float2bfloat16_rn(v);
        g_Wth[u] = h;
        g_Wtl[u] = __float2bfloat16_rn(v - __bfloat162float(h));
        return;
    }
    int j = u - 12 * 32 * 40;
    if (j < 12 * 32) {
        int lh = j / 32, f = j % 32;
        float s = 0.f, d = 0.f;
        if (f < 26) {
            for (int o = 0; o < 26; o++) {
                float wv = W[((size_t)lh * 26 + f) * 26 + o];
                s = fmaf(wv, a_src[lh * 26 + o], s);
                d = fmaf(wv, a_dst[lh * 26 + o], d);
            }
        }
        g_wsrc[j] = s;
        g_wdst[j] = d;
    }
}

// =====================================================================
// GAT: R8 structure + augmented-K on STEP 1 ONLY.
// X_aug [26 f][88]: cols 0-25 X_hi(j), 26-51 X_hi(j), 52-77 X_lo(j), pad 0.
// alpha [26 i][88]: [E_hi | E_lo | E_hi], pads zero, lanes<26 write.
// Step1: one GEMM, 5 k16-tiles (40 MMAs) vs 3x2 tiles (48 MMAs).
// Step2: unchanged R8 (register Y->A conversion, W 80B stride, 48 MMAs).
// =====================================================================
#define RSTR  176
#define XROW  4576            // 26 * 176
#define XAO   0               // 8 * 4576 = 36608
#define AYO   36608           // 8 * 4576 -> 73216
#define WTH   73216           // 10240
#define WTL   83456           // 10240
#define SDST  93696           // 8 * 128 floats = 4096
#define SWS   97792
#define SWD   98304
#define GAT_SMEM 98816

__global__ __launch_bounds__(256, 2)
void gat_tc(const float* __restrict__ x)
{
    extern __shared__ char sm[];
    const uint32_t sb = smem_u32(sm);
    const int tid = threadIdx.x, w = tid >> 5, lane = tid & 31;
    const int b = blockIdx.x * 8 + w;
    const int g = lane >> 2, tc2 = (lane & 3) * 2;

    // zero X_aug + alpha regions once (pads stay zero forever)
    {
        uint4* p = (uint4*)(sm + XAO);
        for (int i = tid; i < 73216 / 16; i += 256)
            p[i] = make_uint4(0, 0, 0, 0);
    }
    __syncthreads();

    __nv_bfloat16* xa = (__nv_bfloat16*)(sm + XAO + w * XROW);  // [26 f][88]
    float* sdst = (float*)(sm + SDST) + w * 128;                // [4 h][32 j]
    float* sws  = (float*)(sm + SWS);
    float* swd  = (float*)(sm + SWD);

    const uint32_t xaA = sb + XAO + w * XROW;
    const uint32_t ayA = sb + AYO + w * XROW;

    // stage x (layer 0): X_aug = [X_hi | X_hi | X_lo]
    for (int idx = lane; idx < KDIM; idx += 32) {
        int j = idx / 26, f = idx % 26;
        float v = x[(size_t)b * KDIM + idx];
        __nv_bfloat16 h = __float2bfloat16_rn(v);
        __nv_bfloat16 lo = __float2bfloat16_rn(v - __bfloat162float(h));
        xa[f * 88 + j]      = h;
        xa[f * 88 + 26 + j] = h;
        xa[f * 88 + 52 + j] = lo;
    }

    const int rpat = lane & 15;
    const int chalf = (lane >> 4) * 8;

    for (int l = 0; l < 3; l++) {
        __syncthreads();   // X writes done; W buffer free
        {
            const uint4* s0 = (const uint4*)(g_Wth + l * 5120);
            const uint4* s1 = (const uint4*)(g_Wtl + l * 5120);
            uint4* d0 = (uint4*)(sm + WTH);
            uint4* d1 = (uint4*)(sm + WTL);
            for (int i = tid; i < 640; i += 256) { d0[i] = s0[i]; d1[i] = s1[i]; }
            if (tid < 128) {
                sws[tid] = g_wsrc[l * 128 + tid];
                swd[tid] = g_wdst[l * 128 + tid];
            }
        }
        __syncthreads();

        // ---- scores: lane = node index ----
        float ssrc[4];
        {
            float xi[26];
            #pragma unroll
            for (int f = 0; f < 26; f++)
                xi[f] = __bfloat162float(xa[f * 88 + lane]) +
                        __bfloat162float(xa[f * 88 + 52 + lane]);
            #pragma unroll
            for (int h = 0; h < 4; h++) {
                float s = 0.f, d = 0.f;
                #pragma unroll
                for (int f = 0; f < 26; f++) {
                    s = fmaf(xi[f], sws[h * 32 + f], s);
                    d = fmaf(xi[f], swd[h * 32 + f], d);
                }
                ssrc[h] = s;
                sdst[h * 32 + lane] = d;
            }
        }
        __syncwarp();

        float outf[2][4][4];
        #pragma unroll
        for (int mt = 0; mt < 2; mt++)
            #pragma unroll
            for (int nt = 0; nt < 4; nt++)
                #pragma unroll
                for (int q = 0; q < 4; q++) outf[mt][nt][q] = 0.f;

        for (int h = 0; h < 4; h++) {
            // ---- softmax (normalized) -> alpha_aug, lanes < 26 ----
            {
                float e[NN];
                float m = -1e30f;
                #pragma unroll
                for (int j = 0; j < NN; j++) {
                    float v = ssrc[h] + sdst[h * 32 + j];
                    v = fmaxf(v, 0.2f * v);
                    e[j] = v;
                    m = fmaxf(m, v);
                }
                float su = 0.f;
                #pragma unroll
                for (int j = 0; j < NN; j++) {
                    float p = __expf(e[j] - m);
                    e[j] = p;
                    su += p;
                }
                const float inv = 1.0f / su;
                if (lane < 26) {
                    const uint32_t rowA = ayA + (uint32_t)lane * RSTR;
                    #pragma unroll
                    for (int jj = 0; jj < 13; jj++) {
                        uint32_t hi, lo;
                        split2(e[2 * jj] * inv, e[2 * jj + 1] * inv, hi, lo);
                        sts32(rowA + 4 * jj, hi);           // seg0: E_hi
                        sts32(rowA + 52 + 4 * jj, lo);      // seg1: E_lo
                        sts32(rowA + 104 + 4 * jj, hi);     // seg2: E_hi
                    }
                }
            }
            __syncwarp();

            // ---- step 1 (augmented-K): Y = E_aug @ X_aug, 5 k-tiles ----
            float Yf[2][4][4];
            #pragma unroll
            for (int mt = 0; mt < 2; mt++)
                #pragma unroll
                for (int nt = 0; nt < 4; nt++)
                    #pragma unroll
                    for (int q = 0; q < 4; q++) Yf[mt][nt][q] = 0.f;

            #pragma unroll
            for (int ks = 0; ks < 5; ks++) {
                const uint32_t cb = (uint32_t)(ks * 16 + chalf) * 2;
                uint32_t Af[2][4], Xf[2][4];
                #pragma unroll
                for (int mt = 0; mt < 2; mt++)
                    ldsm4(Af[mt], ayA + (uint32_t)(mt * 16 + rpat) * RSTR + cb);
                #pragma unroll
                for (int nt = 0; nt < 2; nt++)
                    ldsm4(Xf[nt], xaA + (uint32_t)(nt * 16 + rpat) * RSTR + cb);
                #pragma unroll
                for (int mt = 0; mt < 2; mt++)
                    #pragma unroll
                    for (int nt = 0; nt < 2; nt++) {
                        mma16816(Yf[mt][nt * 2],     Af[mt], Xf[nt][0], Xf[nt][2]);
                        mma16816(Yf[mt][nt * 2 + 1], Af[mt], Xf[nt][1], Xf[nt][3]);
                    }
            }

            // ---- in-register C -> A fragment conversion (R8) ----
            uint32_t YAh[2][2][4], YAl[2][2][4];
            #pragma unroll
            for (int mt = 0; mt < 2; mt++)
                #pragma unroll
                for (int ks = 0; ks < 2; ks++) {
                    split2(Yf[mt][2 * ks][0],     Yf[mt][2 * ks][1],     YAh[mt][ks][0], YAl[mt][ks][0]);
                    split2(Yf[mt][2 * ks][2],     Yf[mt][2 * ks][3],     YAh[mt][ks][1], YAl[mt][ks][1]);
                    split2(Yf[mt][2 * ks + 1][0], Yf[mt][2 * ks + 1][1], YAh[mt][ks][2], YAl[mt][ks][2]);
                    split2(Yf[mt][2 * ks + 1][2], Yf[mt][2 * ks + 1][3], YAh[mt][ks][3], YAl[mt][ks][3]);
                }

            // ---- step 2 (R8): out += Y @ W_h, 3-term, 48 MMAs ----
            #pragma unroll
            for (int ks = 0; ks < 2; ks++) {
                uint32_t Wh[2][4], Wl[2][4];
                #pragma unroll
                for (int ot = 0; ot < 2; ot++) {
                    uint32_t off = (uint32_t)((ot * 16 + rpat) * 80 + (ks * 16 + chalf) * 2);
                    ldsm4(Wh[ot], sb + WTH + h * 2560 + off);
                    ldsm4(Wl[ot], sb + WTL + h * 2560 + off);
                }
                #pragma unroll
                for (int mt = 0; mt < 2; mt++)
                    #pragma unroll
                    for (int ot = 0; ot < 2; ot++) {
                        mma16816(outf[mt][ot * 2],     YAh[mt][ks], Wh[ot][0], Wh[ot][2]);
                        mma16816(outf[mt][ot * 2 + 1], YAh[mt][ks], Wh[ot][1], Wh[ot][3]);
                        mma16816(outf[mt][ot * 2],     YAh[mt][ks], Wl[ot][0], Wl[ot][2]);
                        mma16816(outf[mt][ot * 2 + 1], YAh[mt][ks], Wl[ot][1], Wl[ot][3]);
                        mma16816(outf[mt][ot * 2],     YAl[mt][ks], Wh[ot][0], Wh[ot][2]);
                        mma16816(outf[mt][ot * 2 + 1], YAl[mt][ks], Wh[ot][1], Wh[ot][3]);
                    }
            }
        } // heads

        // ---- epilogue: mean + ELU -> next X_aug or final global split ----
        if (l < 2) {
            #pragma unroll
            for (int mt = 0; mt < 2; mt++)
                #pragma unroll
                for (int nt = 0; nt < 4; nt++) {
                    const int col = nt * 8 + tc2;   // feature f
                    if (col < 26) {
                        #pragma unroll
                        for (int hf = 0; hf < 2; hf++) {
                            const int row = mt * 16 + g + hf * 8;   // node j
                            if (row < 26) {
                                float v0 = actelu(outf[mt][nt][hf * 2]     * 0.25f);
                                float v1 = actelu(outf[mt][nt][hf * 2 + 1] * 0.25f);
                                __nv_bfloat16 h0 = __float2bfloat16_rn(v0);
                                __nv_bfloat16 l0 = __float2bfloat16_rn(v0 - __bfloat162float(h0));
                                __nv_bfloat16 h1 = __float2bfloat16_rn(v1);
                                __nv_bfloat16 l1 = __float2bfloat16_rn(v1 - __bfloat162float(h1));
                                uint16_t u;
                                const uint32_t b0a = xaA + (uint32_t)col * RSTR;
                                const uint32_t b1a = xaA + (uint32_t)(col + 1) * RSTR;
                                memcpy(&u, &h0, 2);
                                sts16(b0a + 2 * row, u);
                                sts16(b0a + 52 + 2 * row, u);
                                memcpy(&u, &l0, 2);
                                sts16(b0a + 104 + 2 * row, u);
                                memcpy(&u, &h1, 2);
                                sts16(b1a + 2 * row, u);
                                sts16(b1a + 52 + 2 * row, u);
                                memcpy(&u, &l1, 2);
                                sts16(b1a + 104 + 2 * row, u);
                            }
                        }
                    }
                }
        } else {
            #pragma unroll
            for (int mt = 0; mt < 2; mt++)
                #pragma unroll
                for (int nt = 0; nt < 4; nt++) {
                    const int col = nt * 8 + tc2;
                    if (col < 26) {
                        #pragma unroll
                        for (int hf = 0; hf < 2; hf++) {
                            const int row = mt * 16 + g + hf * 8;
                            if (row < 26) {
                                float v0 = actelu(outf[mt][nt][hf * 2]     * 0.25f);
                                float v1 = actelu(outf[mt][nt][hf * 2 + 1] * 0.25f);
                                uint32_t hi, lo;
                                split2(v0, v1, hi, lo);
                                size_t o = (size_t)b * KPAD + row * 26 + col;
                                *(uint32_t*)&g_Ahi[o] = hi;
                                *(uint32_t*)&g_Alo[o] = lo;
                            }
                        }
                    }
                }
            if (lane < 28) {
                g_Ahi[(size_t)b * KPAD + KDIM + lane] = __float2bfloat16_rn(0.f);
                g_Alo[(size_t)b * KPAD + KDIM + lane] = __float2bfloat16_rn(0.f);
            }
        }
    } // layers
}

// =====================================================================
// MLP via mma.sync bf16 (3-term split), hoisted loads — R8 verbatim.
// =====================================================================
#define STAGE_BYTES 51200
#define MLP_SMEM (2 * STAGE_BYTES)

__device__ __forceinline__ void copy_chunk(uint32_t smbase, int stage, int chunk,
                                           int row0, int tid)
{
    const uint32_t sbs = smbase + stage * STAGE_BYTES;
    #pragma unroll
    for (int k = 0; k < 10; k++) {
        int u = tid + k * 256;
        if (u < 512) {
            int t = u >> 8, r = (u & 255) >> 2, seg = u & 3;
            const __nv_bfloat16* base = t ? g_Alo : g_Ahi;
            const __nv_bfloat16* src = base + (size_t)(row0 + r) * KPAD + chunk * 32 + seg * 8;
            cp16(sbs + t * 5120 + r * 80 + seg * 16, src);
        } else {
            int v = u - 512;
            int t = v >> 10, r = (v & 1023) >> 2, seg = v & 3;
            const __nv_bfloat16* base = t ? g_Blo : g_Bhi;
            const __nv_bfloat16* src = base + (size_t)r * KPAD + chunk * 32 + seg * 8;
            cp16(sbs + 10240 + t * 20480 + r * 80 + seg * 16, src);
        }
    }
}

__global__ __launch_bounds__(256, 2)
void mlp_mma(const float* __restrict__ b1,
             const float* __restrict__ W2,
             const float* __restrict__ b2,
             float* __restrict__ out)
{
    extern __shared__ __align__(16) char dsm[];
    __shared__ float sb1[HID];
    __shared__ float sW2[HID * 3];
    __shared__ float sb2s[3];
    __shared__ float red[64][13];

    const int tid = threadIdx.x, wid = tid >> 5, lane = tid & 31;
    const int warp_m = wid & 1;
    const int warp_n = wid >> 1;
    const int row0 = blockIdx.x * 64;

    if (tid < HID) sb1[tid] = b1[tid];
    for (int i = tid; i < HID * 3; i += 256) sW2[i] = W2[i];
    if (tid < 3) sb2s[tid] = b2[tid];

    const uint32_t smbase = smem_u32(dsm);

    float acc[2][8][4];
    #pragma unroll
    for (int mt = 0; mt < 2; mt++)
        #pragma unroll
        for (int nt = 0; nt < 8; nt++)
            #pragma unroll
            for (int q = 0; q < 4; q++) acc[mt][nt][q] = 0.f;

    copy_chunk(smbase, 0, 0, row0, tid);
    CP_COMMIT();

    const int rpat = lane & 15;

    for (int c = 0; c < NCHUNK; c++) {
        const int s = c & 1;
        if (c + 1 < NCHUNK) {
            copy_chunk(smbase, s ^ 1, c + 1, row0, tid);
            CP_COMMIT();
            CP_WAIT1();
        } else {
            CP_WAIT0();
        }
        __syncthreads();

        const uint32_t stB = smbase + s * STAGE_BYTES;
        #pragma unroll
        for (int ks = 0; ks < 2; ks++) {
            const int cpat = ks * 16 + (lane >> 4) * 8;

            uint32_t ah[2][4], al[2][4], bh[4][4], bl[4][4];
            #pragma unroll
            for (int mt = 0; mt < 2; mt++) {
                const uint32_t a_off =
                    (uint32_t)((warp_m * 32 + mt * 16 + rpat) * 80 + cpat * 2);
                ldsm4(ah[mt], stB + a_off);
                ldsm4(al[mt], stB + 5120 + a_off);
            }
            #pragma unroll
            for (int np = 0; np < 4; np++) {
                const uint32_t b_off =
                    (uint32_t)((warp_n * 64 + np * 16 + rpat) * 80 + cpat * 2);
                ldsm4(bh[np], stB + 10240 + b_off);
                ldsm4(bl[np], stB + 30720 + b_off);
            }

            #pragma unroll
            for (int mt = 0; mt < 2; mt++)
                #pragma unroll
                for (int np = 0; np < 4; np++) {
                    mma16816(acc[mt][np * 2 + 0], ah[mt], bh[np][0], bh[np][2]);
                    mma16816(acc[mt][np * 2 + 1], ah[mt], bh[np][1], bh[np][3]);
                    mma16816(acc[mt][np * 2 + 0], al[mt], bh[np][0], bh[np][2]);
                    mma16816(acc[mt][np * 2 + 1], al[mt], bh[np][1], bh[np][3]);
                    mma16816(acc[mt][np * 2 + 0], ah[mt], bl[np][0], bl[np][2]);
                    mma16816(acc[mt][np * 2 + 1], ah[mt], bl[np][1], bl[np][3]);
                }
        }
        __syncthreads();
    }

    #pragma unroll
    for (int mt = 0; mt < 2; mt++) {
        #pragma unroll
        for (int half = 0; half < 2; half++) {
            float s0 = 0.f, s1 = 0.f, s2 = 0.f;
            #pragma unroll
            for (int nt = 0; nt < 8; nt++) {
                const int col = warp_n * 64 + nt * 8 + (lane & 3) * 2;
                float v0 = acc[mt][nt][half * 2 + 0] + sb1[col];
                v0 = fmaxf(v0, 0.2f * v0);
                float v1 = acc[mt][nt][half * 2 + 1] + sb1[col + 1];
                v1 = fmaxf(v1, 0.2f * v1);
                s0 += v0 * sW2[col * 3 + 0] + v1 * sW2[(col + 1) * 3 + 0];
                s1 += v0 * sW2[col * 3 + 1] + v1 * sW2[(col + 1) * 3 + 1];
                s2 += v0 * sW2[col * 3 + 2] + v1 * sW2[(col + 1) * 3 + 2];
            }
            s0 += __shfl_xor_sync(0xffffffffu, s0, 1);
            s0 += __shfl_xor_sync(0xffffffffu, s0, 2);
            s1 += __shfl_xor_sync(0xffffffffu, s1, 1);
            s1 += __shfl_xor_sync(0xffffffffu, s1, 2);
            s2 += __shfl_xor_sync(0xffffffffu, s2, 1);
            s2 += __shfl_xor_sync(0xffffffffu, s2, 2);
            if ((lane & 3) == 0) {
                const int row = warp_m * 32 + mt * 16 + half * 8 + (lane >> 2);
                red[row][warp_n * 3 + 0] = s0;
                red[row][warp_n * 3 + 1] = s1;
                red[row][warp_n * 3 + 2] = s2;
            }
        }
    }
    __syncthreads();
    if (tid < 64) {
        const int row = tid;
        #pragma unroll
        for (int oc = 0; oc < 3; oc++) {
            float v = red[row][oc] + red[row][3 + oc] + red[row][6 + oc] +
                      red[row][9 + oc] + sb2s[oc];
            out[(size_t)(row0 + row) * 3 + oc] = v;
        }
    }
}

// =====================================================================
// launch
// =====================================================================
extern "C" void kernel_launch(void* const* d_in, const int* in_sizes, int n_in,
                              void* d_out, int out_size)
{
    const float* x     = (const float*)d_in[1];
    const float* W     = (const float*)d_in[2];
    const float* a_src = (const float*)d_in[3];
    const float* a_dst = (const float*)d_in[4];
    const float* W1    = (const float*)d_in[5];
    const float* b1    = (const float*)d_in[6];
    const float* W2    = (const float*)d_in[7];
    const float* b2    = (const float*)d_in[8];
    float* out = (float*)d_out;

    const int batch = in_sizes[1] / KDIM;   // 16384

    cudaFuncSetAttribute(gat_tc, cudaFuncAttributeMaxDynamicSharedMemorySize, GAT_SMEM);
    cudaFuncSetAttribute(mlp_mma, cudaFuncAttributeMaxDynamicSharedMemorySize, MLP_SMEM);

    const int prep_total = 256 * KPAD + 12 * 32 * 40 + 12 * 32;
    prep_all<<<(prep_total + 255) / 256, 256>>>(W1, W, a_src, a_dst);
    gat_tc<<<batch / 8, 256, GAT_SMEM>>>(x);
    mlp_mma<<<batch / 64, 256, MLP_SMEM>>>(b1, W2, b2, out);
    (void)n_in; (void)out_size;
}

// round 16
// speedup vs baseline: 1.2739x; 1.1623x over previous
#include <cuda_runtime.h>
#include <cuda_bf16.h>
#include <cuda_fp16.h>
#include <cstdint>
#include <cstddef>
#include <cstring>

// ---------------- problem constants ----------------
#define NN       26
#define KDIM     676
#define KPAD     704          // 22 * 32
#define NCHUNK   22
#define HID      256

// GAT output as SINGLE fp16 [B, KPAD] (error 2^-12, corrected by nothing --
// the MLP's W carries the split instead)
__device__ __half g_Af16[16384 * KPAD];
// W1^T fp16 2-term split: [256 n][KPAD k]
__device__ __half g_W1hi[256 * KPAD];
__device__ __half g_W1lo[256 * KPAD];
// GAT weights, transposed + padded + split (bf16, unchanged): [12 lh][32 o][40 f]
__device__ __nv_bfloat16 g_Wth[12 * 32 * 40];
__device__ __nv_bfloat16 g_Wtl[12 * 32 * 40];
// score vectors wsrc/wdst = W @ a_*: [12 lh][32 f]
__device__ float g_wsrc[12 * 32];
__device__ float g_wdst[12 * 32];

// ---------------- common helpers ----------------
__device__ __forceinline__ uint32_t smem_u32(const void* p) {
    uint32_t a;
    asm("{ .reg .u64 t; cvta.to.shared.u64 t, %1; cvt.u32.u64 %0, t; }" : "=r"(a) : "l"(p));
    return a;
}
__device__ __forceinline__ void ldsm4(uint32_t* d, uint32_t addr) {
    asm volatile("ldmatrix.sync.aligned.m8n8.x4.shared.b16 {%0,%1,%2,%3}, [%4];"
                 : "=r"(d[0]), "=r"(d[1]), "=r"(d[2]), "=r"(d[3]) : "r"(addr));
}
__device__ __forceinline__ void mma16816(float* c, const uint32_t* a, uint32_t b0, uint32_t b1) {
    asm volatile(
        "mma.sync.aligned.m16n8k16.row.col.f32.bf16.bf16.f32 "
        "{%0,%1,%2,%3}, {%4,%5,%6,%7}, {%8,%9}, {%0,%1,%2,%3};"
        : "+f"(c[0]), "+f"(c[1]), "+f"(c[2]), "+f"(c[3])
        : "r"(a[0]), "r"(a[1]), "r"(a[2]), "r"(a[3]), "r"(b0), "r"(b1));
}
__device__ __forceinline__ void mma16816h(float* c, const uint32_t* a, uint32_t b0, uint32_t b1) {
    asm volatile(
        "mma.sync.aligned.m16n8k16.row.col.f32.f16.f16.f32 "
        "{%0,%1,%2,%3}, {%4,%5,%6,%7}, {%8,%9}, {%0,%1,%2,%3};"
        : "+f"(c[0]), "+f"(c[1]), "+f"(c[2]), "+f"(c[3])
        : "r"(a[0]), "r"(a[1]), "r"(a[2]), "r"(a[3]), "r"(b0), "r"(b1));
}
__device__ __forceinline__ void cp16(uint32_t dst, const void* src) {
    asm volatile("cp.async.ca.shared.global [%0], [%1], 16;" :: "r"(dst), "l"(src) : "memory");
}
#define CP_COMMIT() asm volatile("cp.async.commit_group;" ::: "memory")
#define CP_WAIT1()  asm volatile("cp.async.wait_group 1;" ::: "memory")
#define CP_WAIT0()  asm volatile("cp.async.wait_group 0;" ::: "memory")

// split two floats into packed bf16x2 hi + lo correction
__device__ __forceinline__ void split2(float a, float b, uint32_t& hi, uint32_t& lo) {
    __nv_bfloat162 h = __floats2bfloat162_rn(a, b);
    float ra = a - __bfloat162float(h.x);
    float rb = b - __bfloat162float(h.y);
    __nv_bfloat162 l = __floats2bfloat162_rn(ra, rb);
    memcpy(&hi, &h, 4);
    memcpy(&lo, &l, 4);
}
__device__ __forceinline__ float actelu(float v) {
    return v > 0.f ? v : (__expf(v) - 1.f);
}

// =====================================================================
// merged prep kernel: W1^T fp16 2-term split + GAT bf16 split (R8)
// =====================================================================
__global__ void prep_all(const float* __restrict__ W1,
                         const float* __restrict__ W,
                         const float* __restrict__ a_src,
                         const float* __restrict__ a_dst)
{
    int i = blockIdx.x * 256 + threadIdx.x;
    if (i < 256 * KPAD) {
        int n = i / KPAD, k = i % KPAD;
        float v = (k < KDIM) ? W1[(size_t)k * HID + n] : 0.f;
        __half h = __float2half_rn(v);
        g_W1hi[i] = h;
        g_W1lo[i] = __float2half_rn(v - __half2float(h));
        return;
    }
    int u = i - 256 * KPAD;
    if (u < 12 * 32 * 40) {
        int lh = u / 1280, r = u % 1280, o = r / 40, f = r % 40;
        float v = (o < 26 && f < 26) ? W[((size_t)lh * 26 + f) * 26 + o] : 0.f;
        __nv_bfloat16 h = __float2bfloat16_rn(v);
        g_Wth[u] = h;
        g_Wtl[u] = __float2bfloat16_rn(v - __bfloat162float(h));
        return;
    }
    int j = u - 12 * 32 * 40;
    if (j < 12 * 32) {
        int lh = j / 32, f = j % 32;
        float s = 0.f, d = 0.f;
        if (f < 26) {
            for (int o = 0; o < 26; o++) {
                float wv = W[((size_t)lh * 26 + f) * 26 + o];
                s = fmaf(wv, a_src[lh * 26 + o], s);
                d = fmaf(wv, a_dst[lh * 26 + o], d);
            }
        }
        g_wsrc[j] = s;
        g_wdst[j] = d;
    }
}

// =====================================================================
// GAT on tensor cores — R8 verbatim except final store = single fp16.
// =====================================================================
#define XTH 0
#define XTL 20480
#define APH 40960
#define APL 61440
#define WTH 81920
#define WTL 92160
#define SDST 102400
#define SWS 106496
#define SWD 107008
#define GAT_SMEM 107520

__global__ __launch_bounds__(256, 2)
void gat_tc(const float* __restrict__ x)
{
    extern __shared__ char sm[];
    const uint32_t sb = smem_u32(sm);
    const int tid = threadIdx.x, w = tid >> 5, lane = tid & 31;
    const int b = blockIdx.x * 8 + w;

    // zero xT buffers once (pads stay zero forever)
    {
        uint4* p = (uint4*)(sm + XTH);
        for (int i = tid; i < (20480 * 2) / 16; i += 256)
            p[i] = make_uint4(0, 0, 0, 0);
    }
    __syncthreads();

    __nv_bfloat16* xth = (__nv_bfloat16*)(sm + XTH) + w * 1280;   // [32 f][40 j]
    __nv_bfloat16* xtl = (__nv_bfloat16*)(sm + XTL) + w * 1280;
    __nv_bfloat16* aph = (__nv_bfloat16*)(sm + APH) + w * 1280;   // [32 i][40 j]
    __nv_bfloat16* apl = (__nv_bfloat16*)(sm + APL) + w * 1280;
    float* sdst = (float*)(sm + SDST) + w * 128;                  // [4 h][32 j]
    float* sws  = (float*)(sm + SWS);                             // [4 h][32 f]
    float* swd  = (float*)(sm + SWD);

    // stage x (layer 0): transposed bf16 split
    for (int idx = lane; idx < KDIM; idx += 32) {
        int i = idx / 26, f = idx % 26;
        float v = x[(size_t)b * KDIM + idx];
        __nv_bfloat16 h = __float2bfloat16_rn(v);
        xth[f * 40 + i] = h;
        xtl[f * 40 + i] = __float2bfloat16_rn(v - __bfloat162float(h));
    }

    const int rpat = lane & 15;
    const int chalf = (lane >> 4) * 8;
    const uint32_t xthA = sb + XTH + w * 2560;
    const uint32_t xtlA = sb + XTL + w * 2560;
    const uint32_t aphA = sb + APH + w * 2560;
    const uint32_t aplA = sb + APL + w * 2560;

    for (int l = 0; l < 3; l++) {
        __syncthreads();   // xT writes done; W buffer free
        {
            const uint4* s0 = (const uint4*)(g_Wth + l * 5120);
            const uint4* s1 = (const uint4*)(g_Wtl + l * 5120);
            uint4* d0 = (uint4*)(sm + WTH);
            uint4* d1 = (uint4*)(sm + WTL);
            for (int i = tid; i < 640; i += 256) { d0[i] = s0[i]; d1[i] = s1[i]; }
            if (tid < 128) {
                ((float*)(sm + SWS))[tid] = g_wsrc[l * 128 + tid];
                ((float*)(sm + SWD))[tid] = g_wdst[l * 128 + tid];
            }
        }
        __syncthreads();

        // ---- scores: lane = node index ----
        float ssrc[4];
        {
            float xi[26];
            #pragma unroll
            for (int f = 0; f < 26; f++)
                xi[f] = __bfloat162float(xth[f * 40 + lane]) +
                        __bfloat162float(xtl[f * 40 + lane]);
            #pragma unroll
            for (int h = 0; h < 4; h++) {
                float s = 0.f, d = 0.f;
                #pragma unroll
                for (int f = 0; f < 26; f++) {
                    s = fmaf(xi[f], sws[h * 32 + f], s);
                    d = fmaf(xi[f], swd[h * 32 + f], d);
                }
                ssrc[h] = s;
                sdst[h * 32 + lane] = d;
            }
        }
        __syncwarp();

        float outf[2][4][4];
        #pragma unroll
        for (int mt = 0; mt < 2; mt++)
            #pragma unroll
            for (int nt = 0; nt < 4; nt++)
                #pragma unroll
                for (int q = 0; q < 4; q++) outf[mt][nt][q] = 0.f;

        for (int h = 0; h < 4; h++) {
            // ---- softmax row (lane = i) ----
            float e[NN];
            float m = -1e30f;
            #pragma unroll
            for (int j = 0; j < NN; j++) {
                float v = ssrc[h] + sdst[h * 32 + j];
                v = fmaxf(v, 0.2f * v);
                e[j] = v;
                m = fmaxf(m, v);
            }
            float su = 0.f;
            #pragma unroll
            for (int j = 0; j < NN; j++) {
                float p = __expf(e[j] - m);
                e[j] = p;
                su += p;
            }
            const float inv = 1.0f / su;
            #pragma unroll
            for (int jj = 0; jj < 16; jj++) {
                float a0 = (2 * jj < 26) ? e[(2 * jj < 26) ? 2 * jj : 0] * inv : 0.f;
                float a1 = (2 * jj + 1 < 26) ? e[(2 * jj + 1 < 26) ? 2 * jj + 1 : 0] * inv : 0.f;
                uint32_t hi, lo;
                split2(a0, a1, hi, lo);
                *(uint32_t*)(aph + lane * 40 + 2 * jj) = hi;
                *(uint32_t*)(apl + lane * 40 + 2 * jj) = lo;
            }
            __syncwarp();

            // ---- step 1: Y = alpha @ x  (3-term split) ----
            float Yf[2][4][4];
            #pragma unroll
            for (int mt = 0; mt < 2; mt++)
                #pragma unroll
                for (int nt = 0; nt < 4; nt++)
                    #pragma unroll
                    for (int q = 0; q < 4; q++) Yf[mt][nt][q] = 0.f;

            #pragma unroll
            for (int ks = 0; ks < 2; ks++) {
                uint32_t Ah[2][4], Al[2][4], Xh[2][4], Xl[2][4];
                #pragma unroll
                for (int mt = 0; mt < 2; mt++) {
                    uint32_t off = (uint32_t)((mt * 16 + rpat) * 80 + (ks * 16 + chalf) * 2);
                    ldsm4(Ah[mt], aphA + off);
                    ldsm4(Al[mt], aplA + off);
                }
                #pragma unroll
                for (int nt = 0; nt < 2; nt++) {
                    uint32_t off = (uint32_t)((nt * 16 + rpat) * 80 + (ks * 16 + chalf) * 2);
                    ldsm4(Xh[nt], xthA + off);
                    ldsm4(Xl[nt], xtlA + off);
                }
                #pragma unroll
                for (int mt = 0; mt < 2; mt++)
                    #pragma unroll
                    for (int nt = 0; nt < 2; nt++) {
                        mma16816(Yf[mt][nt * 2],     Ah[mt], Xh[nt][0], Xh[nt][2]);
                        mma16816(Yf[mt][nt * 2 + 1], Ah[mt], Xh[nt][1], Xh[nt][3]);
                        mma16816(Yf[mt][nt * 2],     Ah[mt], Xl[nt][0], Xl[nt][2]);
                        mma16816(Yf[mt][nt * 2 + 1], Ah[mt], Xl[nt][1], Xl[nt][3]);
                        mma16816(Yf[mt][nt * 2],     Al[mt], Xh[nt][0], Xh[nt][2]);
                        mma16816(Yf[mt][nt * 2 + 1], Al[mt], Xh[nt][1], Xh[nt][3]);
                    }
            }

            // ---- in-register C -> A fragment conversion (split) ----
            uint32_t YAh[2][2][4], YAl[2][2][4];
            #pragma unroll
            for (int mt = 0; mt < 2; mt++)
                #pragma unroll
                for (int ks = 0; ks < 2; ks++) {
                    split2(Yf[mt][2 * ks][0],     Yf[mt][2 * ks][1],     YAh[mt][ks][0], YAl[mt][ks][0]);
                    split2(Yf[mt][2 * ks][2],     Yf[mt][2 * ks][3],     YAh[mt][ks][1], YAl[mt][ks][1]);
                    split2(Yf[mt][2 * ks + 1][0], Yf[mt][2 * ks + 1][1], YAh[mt][ks][2], YAl[mt][ks][2]);
                    split2(Yf[mt][2 * ks + 1][2], Yf[mt][2 * ks + 1][3], YAh[mt][ks][3], YAl[mt][ks][3]);
                }

            // ---- step 2: out += Y @ W_h ----
            #pragma unroll
            for (int ks = 0; ks < 2; ks++) {
                uint32_t Wh[2][4], Wl[2][4];
                #pragma unroll
                for (int ot = 0; ot < 2; ot++) {
                    uint32_t off = (uint32_t)((ot * 16 + rpat) * 80 + (ks * 16 + chalf) * 2);
                    ldsm4(Wh[ot], sb + WTH + h * 2560 + off);
                    ldsm4(Wl[ot], sb + WTL + h * 2560 + off);
                }
                #pragma unroll
                for (int mt = 0; mt < 2; mt++)
                    #pragma unroll
                    for (int ot = 0; ot < 2; ot++) {
                        mma16816(outf[mt][ot * 2],     YAh[mt][ks], Wh[ot][0], Wh[ot][2]);
                        mma16816(outf[mt][ot * 2 + 1], YAh[mt][ks], Wh[ot][1], Wh[ot][3]);
                        mma16816(outf[mt][ot * 2],     YAh[mt][ks], Wl[ot][0], Wl[ot][2]);
                        mma16816(outf[mt][ot * 2 + 1], YAh[mt][ks], Wl[ot][1], Wl[ot][3]);
                        mma16816(outf[mt][ot * 2],     YAl[mt][ks], Wh[ot][0], Wh[ot][2]);
                        mma16816(outf[mt][ot * 2 + 1], YAl[mt][ks], Wh[ot][1], Wh[ot][3]);
                    }
            }
        } // heads

        // ---- epilogue: mean + ELU, write next xT or final fp16 global ----
        const int g = lane >> 2, tc2 = (lane & 3) * 2;
        if (l < 2) {
            #pragma unroll
            for (int mt = 0; mt < 2; mt++)
                #pragma unroll
                for (int nt = 0; nt < 4; nt++) {
                    int col = nt * 8 + tc2;
                    if (col < 26) {
                        #pragma unroll
                        for (int hf = 0; hf < 2; hf++) {
                            int row = mt * 16 + g + hf * 8;
                            if (row < 26) {
                                float v0 = actelu(outf[mt][nt][hf * 2]     * 0.25f);
                                float v1 = actelu(outf[mt][nt][hf * 2 + 1] * 0.25f);
                                __nv_bfloat16 h0 = __float2bfloat16_rn(v0);
                                __nv_bfloat16 h1 = __float2bfloat16_rn(v1);
                                xth[col * 40 + row] = h0;
                                xtl[col * 40 + row] = __float2bfloat16_rn(v0 - __bfloat162float(h0));
                                xth[(col + 1) * 40 + row] = h1;
                                xtl[(col + 1) * 40 + row] = __float2bfloat16_rn(v1 - __bfloat162float(h1));
                            }
                        }
                    }
                }
        } else {
            #pragma unroll
            for (int mt = 0; mt < 2; mt++)
                #pragma unroll
                for (int nt = 0; nt < 4; nt++) {
                    int col = nt * 8 + tc2;
                    if (col < 26) {
                        #pragma unroll
                        for (int hf = 0; hf < 2; hf++) {
                            int row = mt * 16 + g + hf * 8;
                            if (row < 26) {
                                float v0 = actelu(outf[mt][nt][hf * 2]     * 0.25f);
                                float v1 = actelu(outf[mt][nt][hf * 2 + 1] * 0.25f);
                                __half2 hv;
                                hv.x = __float2half_rn(v0);
                                hv.y = __float2half_rn(v1);
                                size_t o = (size_t)b * KPAD + row * 26 + col;
                                *(__half2*)&g_Af16[o] = hv;
                            }
                        }
                    }
                }
            if (lane < 28)
                g_Af16[(size_t)b * KPAD + KDIM + lane] = __float2half_rn(0.f);
        }
    } // layers
}

// =====================================================================
// MLP via mma.sync fp16, 2-TERM: A_f16 @ (W_hi + W_lo).
// Block 64 rows x 256 cols, 8 warps, K-chunks of 32, cp.async 2-stage.
// Per ks: 32 MMAs (vs 48 in bf16 3-term). Fused epilogue unchanged.
// =====================================================================
#define STAGE_BYTES 46080       // A 5120 + Whi 20480 + Wlo 20480
#define MLP_SMEM (2 * STAGE_BYTES)

__device__ __forceinline__ void copy_chunk(uint32_t smbase, int stage, int chunk,
                                           int row0, int tid)
{
    const uint32_t sbs = smbase + stage * STAGE_BYTES;
    #pragma unroll
    for (int k = 0; k < 9; k++) {
        int u = tid + k * 256;
        if (u < 256) {
            int r = u >> 2, seg = u & 3;
            const __half* src = g_Af16 + (size_t)(row0 + r) * KPAD + chunk * 32 + seg * 8;
            cp16(sbs + r * 80 + seg * 16, src);
        } else {
            int v = u - 256;
            int t = v >> 10, r = (v & 1023) >> 2, seg = v & 3;
            const __half* base = t ? g_W1lo : g_W1hi;
            const __half* src = base + (size_t)r * KPAD + chunk * 32 + seg * 8;
            cp16(sbs + 5120 + t * 20480 + r * 80 + seg * 16, src);
        }
    }
}

__global__ __launch_bounds__(256, 2)
void mlp_mma(const float* __restrict__ b1,
             const float* __restrict__ W2,
             const float* __restrict__ b2,
             float* __restrict__ out)
{
    extern __shared__ __align__(16) char dsm[];
    __shared__ float sb1[HID];
    __shared__ float sW2[HID * 3];
    __shared__ float sb2s[3];
    __shared__ float red[64][13];

    const int tid = threadIdx.x, wid = tid >> 5, lane = tid & 31;
    const int warp_m = wid & 1;
    const int warp_n = wid >> 1;
    const int row0 = blockIdx.x * 64;

    if (tid < HID) sb1[tid] = b1[tid];
    for (int i = tid; i < HID * 3; i += 256) sW2[i] = W2[i];
    if (tid < 3) sb2s[tid] = b2[tid];

    const uint32_t smbase = smem_u32(dsm);

    float acc[2][8][4];
    #pragma unroll
    for (int mt = 0; mt < 2; mt++)
        #pragma unroll
        for (int nt = 0; nt < 8; nt++)
            #pragma unroll
            for (int q = 0; q < 4; q++) acc[mt][nt][q] = 0.f;

    copy_chunk(smbase, 0, 0, row0, tid);
    CP_COMMIT();

    const int rpat = lane & 15;

    for (int c = 0; c < NCHUNK; c++) {
        const int s = c & 1;
        if (c + 1 < NCHUNK) {
            copy_chunk(smbase, s ^ 1, c + 1, row0, tid);
            CP_COMMIT();
            CP_WAIT1();
        } else {
            CP_WAIT0();
        }
        __syncthreads();

        const uint32_t stB = smbase + s * STAGE_BYTES;
        #pragma unroll
        for (int ks = 0; ks < 2; ks++) {
            const int cpat = ks * 16 + (lane >> 4) * 8;

            uint32_t ah[2][4], bh[4][4], bl[4][4];
            #pragma unroll
            for (int mt = 0; mt < 2; mt++) {
                const uint32_t a_off =
                    (uint32_t)((warp_m * 32 + mt * 16 + rpat) * 80 + cpat * 2);
                ldsm4(ah[mt], stB + a_off);
            }
            #pragma unroll
            for (int np = 0; np < 4; np++) {
                const uint32_t b_off =
                    (uint32_t)((warp_n * 64 + np * 16 + rpat) * 80 + cpat * 2);
                ldsm4(bh[np], stB + 5120 + b_off);
                ldsm4(bl[np], stB + 25600 + b_off);
            }

            #pragma unroll
            for (int mt = 0; mt < 2; mt++)
                #pragma unroll
                for (int np = 0; np < 4; np++) {
                    mma16816h(acc[mt][np * 2 + 0], ah[mt], bh[np][0], bh[np][2]);
                    mma16816h(acc[mt][np * 2 + 1], ah[mt], bh[np][1], bh[np][3]);
                    mma16816h(acc[mt][np * 2 + 0], ah[mt], bl[np][0], bl[np][2]);
                    mma16816h(acc[mt][np * 2 + 1], ah[mt], bl[np][1], bl[np][3]);
                }
        }
        __syncthreads();
    }

    #pragma unroll
    for (int mt = 0; mt < 2; mt++) {
        #pragma unroll
        for (int half = 0; half < 2; half++) {
            float s0 = 0.f, s1 = 0.f, s2 = 0.f;
            #pragma unroll
            for (int nt = 0; nt < 8; nt++) {
                const int col = warp_n * 64 + nt * 8 + (lane & 3) * 2;
                float v0 = acc[mt][nt][half * 2 + 0] + sb1[col];
                v0 = fmaxf(v0, 0.2f * v0);
                float v1 = acc[mt][nt][half * 2 + 1] + sb1[col + 1];
                v1 = fmaxf(v1, 0.2f * v1);
                s0 += v0 * sW2[col * 3 + 0] + v1 * sW2[(col + 1) * 3 + 0];
                s1 += v0 * sW2[col * 3 + 1] + v1 * sW2[(col + 1) * 3 + 1];
                s2 += v0 * sW2[col * 3 + 2] + v1 * sW2[(col + 1) * 3 + 2];
            }
            s0 += __shfl_xor_sync(0xffffffffu, s0, 1);
            s0 += __shfl_xor_sync(0xffffffffu, s0, 2);
            s1 += __shfl_xor_sync(0xffffffffu, s1, 1);
            s1 += __shfl_xor_sync(0xffffffffu, s1, 2);
            s2 += __shfl_xor_sync(0xffffffffu, s2, 1);
            s2 += __shfl_xor_sync(0xffffffffu, s2, 2);
            if ((lane & 3) == 0) {
                const int row = warp_m * 32 + mt * 16 + half * 8 + (lane >> 2);
                red[row][warp_n * 3 + 0] = s0;
                red[row][warp_n * 3 + 1] = s1;
                red[row][warp_n * 3 + 2] = s2;
            }
        }
    }
    __syncthreads();
    if (tid < 64) {
        const int row = tid;
        #pragma unroll
        for (int oc = 0; oc < 3; oc++) {
            float v = red[row][oc] + red[row][3 + oc] + red[row][6 + oc] +
                      red[row][9 + oc] + sb2s[oc];
            out[(size_t)(row0 + row) * 3 + oc] = v;
        }
    }
}

// =====================================================================
// launch
// =====================================================================
extern "C" void kernel_launch(void* const* d_in, const int* in_sizes, int n_in,
                              void* d_out, int out_size)
{
    const float* x     = (const float*)d_in[1];
    const float* W     = (const float*)d_in[2];
    const float* a_src = (const float*)d_in[3];
    const float* a_dst = (const float*)d_in[4];
    const float* W1    = (const float*)d_in[5];
    const float* b1    = (const float*)d_in[6];
    const float* W2    = (const float*)d_in[7];
    const float* b2    = (const float*)d_in[8];
    float* out = (float*)d_out;

    const int batch = in_sizes[1] / KDIM;   // 16384

    cudaFuncSetAttribute(gat_tc, cudaFuncAttributeMaxDynamicSharedMemorySize, GAT_SMEM);
    cudaFuncSetAttribute(mlp_mma, cudaFuncAttributeMaxDynamicSharedMemorySize, MLP_SMEM);

    const int prep_total = 256 * KPAD + 12 * 32 * 40 + 12 * 32;
    prep_all<<<(prep_total + 255) / 256, 256>>>(W1, W, a_src, a_dst);
    gat_tc<<<batch / 8, 256, GAT_SMEM>>>(x);
    mlp_mma<<<batch / 64, 256, MLP_SMEM>>>(b1, W2, b2, out);
    (void)n_in; (void)out_size;
}

// round 17
// speedup vs baseline: 1.6420x; 1.2890x over previous
#include <cuda_runtime.h>
#include <cuda_bf16.h>
#include <cuda_fp16.h>
#include <cstdint>
#include <cstddef>
#include <cstring>

// ---------------- problem constants ----------------
#define NN       26
#define KDIM     676
#define KPAD     704          // 22 * 32
#define NCHUNK   22
#define HID      256

// GAT output as SINGLE fp16 [B, KPAD]
__device__ __half g_Af16[16384 * KPAD];
// W1^T fp16 2-term split: [256 n][KPAD k]
__device__ __half g_W1hi[256 * KPAD];
__device__ __half g_W1lo[256 * KPAD];
// GAT weights, transposed + padded + fp16 split: [12 lh][32 o][40 f]
__device__ __half g_Wfh[12 * 32 * 40];
__device__ __half g_Wfl[12 * 32 * 40];
// score vectors wsrc/wdst = W @ a_*: [12 lh][32 f]
__device__ float g_wsrc[12 * 32];
__device__ float g_wdst[12 * 32];

// ---------------- common helpers ----------------
__device__ __forceinline__ uint32_t smem_u32(const void* p) {
    uint32_t a;
    asm("{ .reg .u64 t; cvta.to.shared.u64 t, %1; cvt.u32.u64 %0, t; }" : "=r"(a) : "l"(p));
    return a;
}
__device__ __forceinline__ void ldsm4(uint32_t* d, uint32_t addr) {
    asm volatile("ldmatrix.sync.aligned.m8n8.x4.shared.b16 {%0,%1,%2,%3}, [%4];"
                 : "=r"(d[0]), "=r"(d[1]), "=r"(d[2]), "=r"(d[3]) : "r"(addr));
}
__device__ __forceinline__ void mma16816h(float* c, const uint32_t* a, uint32_t b0, uint32_t b1) {
    asm volatile(
        "mma.sync.aligned.m16n8k16.row.col.f32.f16.f16.f32 "
        "{%0,%1,%2,%3}, {%4,%5,%6,%7}, {%8,%9}, {%0,%1,%2,%3};"
        : "+f"(c[0]), "+f"(c[1]), "+f"(c[2]), "+f"(c[3])
        : "r"(a[0]), "r"(a[1]), "r"(a[2]), "r"(a[3]), "r"(b0), "r"(b1));
}
__device__ __forceinline__ void cp16(uint32_t dst, const void* src) {
    asm volatile("cp.async.ca.shared.global [%0], [%1], 16;" :: "r"(dst), "l"(src) : "memory");
}
#define CP_COMMIT() asm volatile("cp.async.commit_group;" ::: "memory")
#define CP_WAIT1()  asm volatile("cp.async.wait_group 1;" ::: "memory")
#define CP_WAIT0()  asm volatile("cp.async.wait_group 0;" ::: "memory")

// pack two floats into one fp16x2 register
__device__ __forceinline__ uint32_t packh2(float a, float b) {
    __half2 h = __floats2half2_rn(a, b);
    uint32_t r;
    memcpy(&r, &h, 4);
    return r;
}
__device__ __forceinline__ float actelu(float v) {
    return v > 0.f ? v : (__expf(v) - 1.f);
}

// =====================================================================
// merged prep kernel: W1^T fp16 2-term + GAT W fp16 2-term + scores
// =====================================================================
__global__ void prep_all(const float* __restrict__ W1,
                         const float* __restrict__ W,
                         const float* __restrict__ a_src,
                         const float* __restrict__ a_dst)
{
    int i = blockIdx.x * 256 + threadIdx.x;
    if (i < 256 * KPAD) {
        int n = i / KPAD, k = i % KPAD;
        float v = (k < KDIM) ? W1[(size_t)k * HID + n] : 0.f;
        __half h = __float2half_rn(v);
        g_W1hi[i] = h;
        g_W1lo[i] = __float2half_rn(v - __half2float(h));
        return;
    }
    int u = i - 256 * KPAD;
    if (u < 12 * 32 * 40) {
        int lh = u / 1280, r = u % 1280, o = r / 40, f = r % 40;
        float v = (o < 26 && f < 26) ? W[((size_t)lh * 26 + f) * 26 + o] : 0.f;
        __half h = __float2half_rn(v);
        g_Wfh[u] = h;
        g_Wfl[u] = __float2half_rn(v - __half2float(h));
        return;
    }
    int j = u - 12 * 32 * 40;
    if (j < 12 * 32) {
        int lh = j / 32, f = j % 32;
        float s = 0.f, d = 0.f;
        if (f < 26) {
            for (int o = 0; o < 26; o++) {
                float wv = W[((size_t)lh * 26 + f) * 26 + o];
                s = fmaf(wv, a_src[lh * 26 + o], s);
                d = fmaf(wv, a_dst[lh * 26 + o], d);
            }
        }
        g_wsrc[j] = s;
        g_wdst[j] = d;
    }
}

// =====================================================================
// GAT on tensor cores, fp16 2-term (R8 skeleton):
//  step1: Y = alpha_f16 @ (X_hi + X_lo)   -- 32 MMAs/head
//  step2: out += Y_f16 @ (W_hi + W_lo)    -- 32 MMAs/head
// X hi/lo exact fp16 split; alpha & Y single fp16 (1 quant each).
// =====================================================================
#define XFH  0               // 8 * 2560 = 20480
#define XFL  20480
#define AFO  40960           // alpha single: 8 * 2560
#define WFH  61440           // 10240
#define WFL  71680           // 10240
#define SDST 81920           // 8 * 128 floats = 4096
#define SWS  86016
#define SWD  86528
#define GAT_SMEM 87040

__global__ __launch_bounds__(256, 2)
void gat_tc(const float* __restrict__ x)
{
    extern __shared__ char sm[];
    const uint32_t sb = smem_u32(sm);
    const int tid = threadIdx.x, w = tid >> 5, lane = tid & 31;
    const int b = blockIdx.x * 8 + w;

    // zero X hi/lo + alpha buffers once (pads stay zero forever)
    {
        uint4* p = (uint4*)(sm + XFH);
        for (int i = tid; i < 61440 / 16; i += 256)
            p[i] = make_uint4(0, 0, 0, 0);
    }
    __syncthreads();

    __half* xfh = (__half*)(sm + XFH) + w * 1280;   // [32 f][40 j]
    __half* xfl = (__half*)(sm + XFL) + w * 1280;
    __half* afp = (__half*)(sm + AFO) + w * 1280;   // [32 i][40 j] single
    float* sdst = (float*)(sm + SDST) + w * 128;    // [4 h][32 j]
    float* sws  = (float*)(sm + SWS);
    float* swd  = (float*)(sm + SWD);

    // stage x (layer 0): transposed fp16 exact split
    for (int idx = lane; idx < KDIM; idx += 32) {
        int i = idx / 26, f = idx % 26;
        float v = x[(size_t)b * KDIM + idx];
        __half h = __float2half_rn(v);
        xfh[f * 40 + i] = h;
        xfl[f * 40 + i] = __float2half_rn(v - __half2float(h));
    }

    const int rpat = lane & 15;
    const int chalf = (lane >> 4) * 8;
    const uint32_t xfhA = sb + XFH + w * 2560;
    const uint32_t xflA = sb + XFL + w * 2560;
    const uint32_t afA  = sb + AFO + w * 2560;

    for (int l = 0; l < 3; l++) {
        __syncthreads();   // X writes done; W buffer free
        {
            const uint4* s0 = (const uint4*)(g_Wfh + l * 5120);
            const uint4* s1 = (const uint4*)(g_Wfl + l * 5120);
            uint4* d0 = (uint4*)(sm + WFH);
            uint4* d1 = (uint4*)(sm + WFL);
            for (int i = tid; i < 640; i += 256) { d0[i] = s0[i]; d1[i] = s1[i]; }
            if (tid < 128) {
                ((float*)(sm + SWS))[tid] = g_wsrc[l * 128 + tid];
                ((float*)(sm + SWD))[tid] = g_wdst[l * 128 + tid];
            }
        }
        __syncthreads();

        // ---- scores: lane = node index ----
        float ssrc[4];
        {
            float xi[26];
            #pragma unroll
            for (int f = 0; f < 26; f++)
                xi[f] = __half2float(xfh[f * 40 + lane]) +
                        __half2float(xfl[f * 40 + lane]);
            #pragma unroll
            for (int h = 0; h < 4; h++) {
                float s = 0.f, d = 0.f;
                #pragma unroll
                for (int f = 0; f < 26; f++) {
                    s = fmaf(xi[f], sws[h * 32 + f], s);
                    d = fmaf(xi[f], swd[h * 32 + f], d);
                }
                ssrc[h] = s;
                sdst[h * 32 + lane] = d;
            }
        }
        __syncwarp();

        float outf[2][4][4];
        #pragma unroll
        for (int mt = 0; mt < 2; mt++)
            #pragma unroll
            for (int nt = 0; nt < 4; nt++)
                #pragma unroll
                for (int q = 0; q < 4; q++) outf[mt][nt][q] = 0.f;

        for (int h = 0; h < 4; h++) {
            // ---- softmax row (lane = i), write alpha single fp16 ----
            float e[NN];
            float m = -1e30f;
            #pragma unroll
            for (int j = 0; j < NN; j++) {
                float v = ssrc[h] + sdst[h * 32 + j];
                v = fmaxf(v, 0.2f * v);
                e[j] = v;
                m = fmaxf(m, v);
            }
            float su = 0.f;
            #pragma unroll
            for (int j = 0; j < NN; j++) {
                float p = __expf(e[j] - m);
                e[j] = p;
                su += p;
            }
            const float inv = 1.0f / su;
            #pragma unroll
            for (int jj = 0; jj < 16; jj++) {
                float a0 = (2 * jj < 26) ? e[(2 * jj < 26) ? 2 * jj : 0] * inv : 0.f;
                float a1 = (2 * jj + 1 < 26) ? e[(2 * jj + 1 < 26) ? 2 * jj + 1 : 0] * inv : 0.f;
                *(uint32_t*)(afp + lane * 40 + 2 * jj) = packh2(a0, a1);
            }
            __syncwarp();

            // ---- step 1: Y = alpha @ (X_hi + X_lo), 32 MMAs ----
            float Yf[2][4][4];
            #pragma unroll
            for (int mt = 0; mt < 2; mt++)
                #pragma unroll
                for (int nt = 0; nt < 4; nt++)
                    #pragma unroll
                    for (int q = 0; q < 4; q++) Yf[mt][nt][q] = 0.f;

            #pragma unroll
            for (int ks = 0; ks < 2; ks++) {
                uint32_t Af[2][4], Xh[2][4], Xl[2][4];
                #pragma unroll
                for (int mt = 0; mt < 2; mt++) {
                    uint32_t off = (uint32_t)((mt * 16 + rpat) * 80 + (ks * 16 + chalf) * 2);
                    ldsm4(Af[mt], afA + off);
                }
                #pragma unroll
                for (int nt = 0; nt < 2; nt++) {
                    uint32_t off = (uint32_t)((nt * 16 + rpat) * 80 + (ks * 16 + chalf) * 2);
                    ldsm4(Xh[nt], xfhA + off);
                    ldsm4(Xl[nt], xflA + off);
                }
                #pragma unroll
                for (int mt = 0; mt < 2; mt++)
                    #pragma unroll
                    for (int nt = 0; nt < 2; nt++) {
                        mma16816h(Yf[mt][nt * 2],     Af[mt], Xh[nt][0], Xh[nt][2]);
                        mma16816h(Yf[mt][nt * 2 + 1], Af[mt], Xh[nt][1], Xh[nt][3]);
                        mma16816h(Yf[mt][nt * 2],     Af[mt], Xl[nt][0], Xl[nt][2]);
                        mma16816h(Yf[mt][nt * 2 + 1], Af[mt], Xl[nt][1], Xl[nt][3]);
                    }
            }

            // ---- C -> A fragment conversion, single fp16 ----
            uint32_t YA[2][2][4];
            #pragma unroll
            for (int mt = 0; mt < 2; mt++)
                #pragma unroll
                for (int ks = 0; ks < 2; ks++) {
                    YA[mt][ks][0] = packh2(Yf[mt][2 * ks][0],     Yf[mt][2 * ks][1]);
                    YA[mt][ks][1] = packh2(Yf[mt][2 * ks][2],     Yf[mt][2 * ks][3]);
                    YA[mt][ks][2] = packh2(Yf[mt][2 * ks + 1][0], Yf[mt][2 * ks + 1][1]);
                    YA[mt][ks][3] = packh2(Yf[mt][2 * ks + 1][2], Yf[mt][2 * ks + 1][3]);
                }

            // ---- step 2: out += Y @ (W_hi + W_lo), 32 MMAs ----
            #pragma unroll
            for (int ks = 0; ks < 2; ks++) {
                uint32_t Wh[2][4], Wl[2][4];
                #pragma unroll
                for (int ot = 0; ot < 2; ot++) {
                    uint32_t off = (uint32_t)((ot * 16 + rpat) * 80 + (ks * 16 + chalf) * 2);
                    ldsm4(Wh[ot], sb + WFH + h * 2560 + off);
                    ldsm4(Wl[ot], sb + WFL + h * 2560 + off);
                }
                #pragma unroll
                for (int mt = 0; mt < 2; mt++)
                    #pragma unroll
                    for (int ot = 0; ot < 2; ot++) {
                        mma16816h(outf[mt][ot * 2],     YA[mt][ks], Wh[ot][0], Wh[ot][2]);
                        mma16816h(outf[mt][ot * 2 + 1], YA[mt][ks], Wh[ot][1], Wh[ot][3]);
                        mma16816h(outf[mt][ot * 2],     YA[mt][ks], Wl[ot][0], Wl[ot][2]);
                        mma16816h(outf[mt][ot * 2 + 1], YA[mt][ks], Wl[ot][1], Wl[ot][3]);
                    }
            }
        } // heads

        // ---- epilogue: mean + ELU, write next X (fp16 split) or final ----
        const int g = lane >> 2, tc2 = (lane & 3) * 2;
        if (l < 2) {
            #pragma unroll
            for (int mt = 0; mt < 2; mt++)
                #pragma unroll
                for (int nt = 0; nt < 4; nt++) {
                    int col = nt * 8 + tc2;
                    if (col < 26) {
                        #pragma unroll
                        for (int hf = 0; hf < 2; hf++) {
                            int row = mt * 16 + g + hf * 8;
                            if (row < 26) {
                                float v0 = actelu(outf[mt][nt][hf * 2]     * 0.25f);
                                float v1 = actelu(outf[mt][nt][hf * 2 + 1] * 0.25f);
                                __half h0 = __float2half_rn(v0);
                                __half h1 = __float2half_rn(v1);
                                xfh[col * 40 + row] = h0;
                                xfl[col * 40 + row] = __float2half_rn(v0 - __half2float(h0));
                                xfh[(col + 1) * 40 + row] = h1;
                                xfl[(col + 1) * 40 + row] = __float2half_rn(v1 - __half2float(h1));
                            }
                        }
                    }
                }
        } else {
            #pragma unroll
            for (int mt = 0; mt < 2; mt++)
                #pragma unroll
                for (int nt = 0; nt < 4; nt++) {
                    int col = nt * 8 + tc2;
                    if (col < 26) {
                        #pragma unroll
                        for (int hf = 0; hf < 2; hf++) {
                            int row = mt * 16 + g + hf * 8;
                            if (row < 26) {
                                float v0 = actelu(outf[mt][nt][hf * 2]     * 0.25f);
                                float v1 = actelu(outf[mt][nt][hf * 2 + 1] * 0.25f);
                                size_t o = (size_t)b * KPAD + row * 26 + col;
                                *(uint32_t*)&g_Af16[o] = packh2(v0, v1);
                            }
                        }
                    }
                }
            if (lane < 28)
                g_Af16[(size_t)b * KPAD + KDIM + lane] = __float2half_rn(0.f);
        }
    } // layers
}

// =====================================================================
// MLP via mma.sync fp16, 2-TERM — R16 verbatim (passing, 62us).
// =====================================================================
#define STAGE_BYTES 46080       // A 5120 + Whi 20480 + Wlo 20480
#define MLP_SMEM (2 * STAGE_BYTES)

__device__ __forceinline__ void copy_chunk(uint32_t smbase, int stage, int chunk,
                                           int row0, int tid)
{
    const uint32_t sbs = smbase + stage * STAGE_BYTES;
    #pragma unroll
    for (int k = 0; k < 9; k++) {
        int u = tid + k * 256;
        if (u < 256) {
            int r = u >> 2, seg = u & 3;
            const __half* src = g_Af16 + (size_t)(row0 + r) * KPAD + chunk * 32 + seg * 8;
            cp16(sbs + r * 80 + seg * 16, src);
        } else {
            int v = u - 256;
            int t = v >> 10, r = (v & 1023) >> 2, seg = v & 3;
            const __half* base = t ? g_W1lo : g_W1hi;
            const __half* src = base + (size_t)r * KPAD + chunk * 32 + seg * 8;
            cp16(sbs + 5120 + t * 20480 + r * 80 + seg * 16, src);
        }
    }
}

__global__ __launch_bounds__(256, 2)
void mlp_mma(const float* __restrict__ b1,
             const float* __restrict__ W2,
             const float* __restrict__ b2,
             float* __restrict__ out)
{
    extern __shared__ __align__(16) char dsm[];
    __shared__ float sb1[HID];
    __shared__ float sW2[HID * 3];
    __shared__ float sb2s[3];
    __shared__ float red[64][13];

    const int tid = threadIdx.x, wid = tid >> 5, lane = tid & 31;
    const int warp_m = wid & 1;
    const int warp_n = wid >> 1;
    const int row0 = blockIdx.x * 64;

    if (tid < HID) sb1[tid] = b1[tid];
    for (int i = tid; i < HID * 3; i += 256) sW2[i] = W2[i];
    if (tid < 3) sb2s[tid] = b2[tid];

    const uint32_t smbase = smem_u32(dsm);

    float acc[2][8][4];
    #pragma unroll
    for (int mt = 0; mt < 2; mt++)
        #pragma unroll
        for (int nt = 0; nt < 8; nt++)
            #pragma unroll
            for (int q = 0; q < 4; q++) acc[mt][nt][q] = 0.f;

    copy_chunk(smbase, 0, 0, row0, tid);
    CP_COMMIT();

    const int rpat = lane & 15;

    for (int c = 0; c < NCHUNK; c++) {
        const int s = c & 1;
        if (c + 1 < NCHUNK) {
            copy_chunk(smbase, s ^ 1, c + 1, row0, tid);
            CP_COMMIT();
            CP_WAIT1();
        } else {
            CP_WAIT0();
        }
        __syncthreads();

        const uint32_t stB = smbase + s * STAGE_BYTES;
        #pragma unroll
        for (int ks = 0; ks < 2; ks++) {
            const int cpat = ks * 16 + (lane >> 4) * 8;

            uint32_t ah[2][4], bh[4][4], bl[4][4];
            #pragma unroll
            for (int mt = 0; mt < 2; mt++) {
                const uint32_t a_off =
                    (uint32_t)((warp_m * 32 + mt * 16 + rpat) * 80 + cpat * 2);
                ldsm4(ah[mt], stB + a_off);
            }
            #pragma unroll
            for (int np = 0; np < 4; np++) {
                const uint32_t b_off =
                    (uint32_t)((warp_n * 64 + np * 16 + rpat) * 80 + cpat * 2);
                ldsm4(bh[np], stB + 5120 + b_off);
                ldsm4(bl[np], stB + 25600 + b_off);
            }

            #pragma unroll
            for (int mt = 0; mt < 2; mt++)
                #pragma unroll
                for (int np = 0; np < 4; np++) {
                    mma16816h(acc[mt][np * 2 + 0], ah[mt], bh[np][0], bh[np][2]);
                    mma16816h(acc[mt][np * 2 + 1], ah[mt], bh[np][1], bh[np][3]);
                    mma16816h(acc[mt][np * 2 + 0], ah[mt], bl[np][0], bl[np][2]);
                    mma16816h(acc[mt][np * 2 + 1], ah[mt], bl[np][1], bl[np][3]);
                }
        }
        __syncthreads();
    }

    #pragma unroll
    for (int mt = 0; mt < 2; mt++) {
        #pragma unroll
        for (int half = 0; half < 2; half++) {
            float s0 = 0.f, s1 = 0.f, s2 = 0.f;
            #pragma unroll
            for (int nt = 0; nt < 8; nt++) {
                const int col = warp_n * 64 + nt * 8 + (lane & 3) * 2;
                float v0 = acc[mt][nt][half * 2 + 0] + sb1[col];
                v0 = fmaxf(v0, 0.2f * v0);
                float v1 = acc[mt][nt][half * 2 + 1] + sb1[col + 1];
                v1 = fmaxf(v1, 0.2f * v1);
                s0 += v0 * sW2[col * 3 + 0] + v1 * sW2[(col + 1) * 3 + 0];
                s1 += v0 * sW2[col * 3 + 1] + v1 * sW2[(col + 1) * 3 + 1];
                s2 += v0 * sW2[col * 3 + 2] + v1 * sW2[(col + 1) * 3 + 2];
            }
            s0 += __shfl_xor_sync(0xffffffffu, s0, 1);
            s0 += __shfl_xor_sync(0xffffffffu, s0, 2);
            s1 += __shfl_xor_sync(0xffffffffu, s1, 1);
            s1 += __shfl_xor_sync(0xffffffffu, s1, 2);
            s2 += __shfl_xor_sync(0xffffffffu, s2, 1);
            s2 += __shfl_xor_sync(0xffffffffu, s2, 2);
            if ((lane & 3) == 0) {
                const int row = warp_m * 32 + mt * 16 + half * 8 + (lane >> 2);
                red[row][warp_n * 3 + 0] = s0;
                red[row][warp_n * 3 + 1] = s1;
                red[row][warp_n * 3 + 2] = s2;
            }
        }
    }
    __syncthreads();
    if (tid < 64) {
        const int row = tid;
        #pragma unroll
        for (int oc = 0; oc < 3; oc++) {
            float v = red[row][oc] + red[row][3 + oc] + red[row][6 + oc] +
                      red[row][9 + oc] + sb2s[oc];
            out[(size_t)(row0 + row) * 3 + oc] = v;
        }
    }
}

// =====================================================================
// launch
// =====================================================================
extern "C" void kernel_launch(void* const* d_in, const int* in_sizes, int n_in,
                              void* d_out, int out_size)
{
    const float* x     = (const float*)d_in[1];
    const float* W     = (const float*)d_in[2];
    const float* a_src = (const float*)d_in[3];
    const float* a_dst = (const float*)d_in[4];
    const float* W1    = (const float*)d_in[5];
    const float* b1    = (const float*)d_in[6];
    const float* W2    = (const float*)d_in[7];
    const float* b2    = (const float*)d_in[8];
    float* out = (float*)d_out;

    const int batch = in_sizes[1] / KDIM;   // 16384

    cudaFuncSetAttribute(gat_tc, cudaFuncAttributeMaxDynamicSharedMemorySize, GAT_SMEM);
    cudaFuncSetAttribute(mlp_mma, cudaFuncAttributeMaxDynamicSharedMemorySize, MLP_SMEM);

    const int prep_total = 256 * KPAD + 12 * 32 * 40 + 12 * 32;
    prep_all<<<(prep_total + 255) / 256, 256>>>(W1, W, a_src, a_dst);
    gat_tc<<<batch / 8, 256, GAT_SMEM>>>(x);
    mlp_mma<<<batch / 64, 256, MLP_SMEM>>>(b1, W2, b2, out);
    (void)n_in; (void)out_size;
}